// round 2
// baseline (speedup 1.0000x reference)
#include <cuda_runtime.h>
#include <math.h>

#define D_MODEL 1024
#define N_HEADS 16
#define D_HEAD  64
#define D_MLP   4096
#define BATCH   2
#define SEQ     2048
#define NTOK    (BATCH*SEQ)   // 4096
#define LN_EPS  1e-5f

// ---------------- scratch (static device globals; no allocation) ----------------
__device__ float g_ln1[NTOK*D_MODEL];
__device__ float g_q  [NTOK*D_MODEL];
__device__ float g_k  [NTOK*D_MODEL];
__device__ float g_v  [NTOK*D_MODEL];
__device__ float g_z  [NTOK*D_MODEL];
__device__ float g_rmid[NTOK*D_MODEL];
__device__ float g_ln2[NTOK*D_MODEL];
__device__ float g_mlp[(size_t)NTOK*D_MLP];

// ---------------- LayerNorm ----------------
// one block per token row, 256 threads, 4 elems/thread
__global__ void ln_kernel(const float* __restrict__ x, const float* __restrict__ w,
                          const float* __restrict__ b, float* __restrict__ out) {
    int row = blockIdx.x;
    const float* xr = x + (size_t)row * D_MODEL;
    float vals[4];
    float s = 0.f, s2 = 0.f;
#pragma unroll
    for (int i = 0; i < 4; i++) {
        float v = xr[threadIdx.x + i*256];
        vals[i] = v; s += v; s2 += v*v;
    }
#pragma unroll
    for (int o = 16; o > 0; o >>= 1) {
        s  += __shfl_xor_sync(0xFFFFFFFFu, s,  o);
        s2 += __shfl_xor_sync(0xFFFFFFFFu, s2, o);
    }
    __shared__ float sh[2][8];
    int wid = threadIdx.x >> 5, lid = threadIdx.x & 31;
    if (lid == 0) { sh[0][wid] = s; sh[1][wid] = s2; }
    __syncthreads();
    s = 0.f; s2 = 0.f;
#pragma unroll
    for (int i = 0; i < 8; i++) { s += sh[0][i]; s2 += sh[1][i]; }
    float mean = s * (1.f/(float)D_MODEL);
    float var  = s2 * (1.f/(float)D_MODEL) - mean*mean;
    float rstd = rsqrtf(var + LN_EPS);
    float* orow = out + (size_t)row * D_MODEL;
#pragma unroll
    for (int i = 0; i < 4; i++) {
        int c = threadIdx.x + i*256;
        orow[c] = (vals[i] - mean) * rstd * w[c] + b[c];
    }
}

// ---------------- GEMM: C[M,N] = A[M,K] @ B + bias (+relu) (+res) ----------------
// 128x128x16 tiles, 256 threads, 8x8 per thread.
// COLMAP 0: B row-major [K,N].
// COLMAP 1: QKV weight [h, d, k] i.e. element (d, n) at (n>>6)*(K*64) + d*64 + (n&63).
template<int COLMAP, bool RELU, bool ADDRES>
__global__ void gemm128(const float* __restrict__ A, const float* __restrict__ B,
                        const float* __restrict__ bias, const float* __restrict__ res,
                        float* __restrict__ C, int M, int N, int K) {
    __shared__ float As[16][128];
    __shared__ float Bs[16][132];   // pad a touch vs. conflicts on stores
    int t = threadIdx.x;
    int bm = blockIdx.y * 128;
    int bn = blockIdx.x * 128;
    int tx = t & 15, ty = t >> 4;

    float acc[8][8];
#pragma unroll
    for (int i = 0; i < 8; i++)
#pragma unroll
        for (int j = 0; j < 8; j++) acc[i][j] = 0.f;

    const int nkt = K >> 4;
    for (int kt = 0; kt < nkt; kt++) {
        int k0 = kt << 4;
        // load A tile: 128 rows x 16 cols = 512 float4, 2 per thread
#pragma unroll
        for (int u = 0; u < 2; u++) {
            int f = t + u*256;
            int row = f >> 2, c4 = f & 3;
            float4 av = *(const float4*)(A + (size_t)(bm + row)*K + k0 + c4*4);
            As[c4*4+0][row] = av.x;
            As[c4*4+1][row] = av.y;
            As[c4*4+2][row] = av.z;
            As[c4*4+3][row] = av.w;
        }
        // load B tile: 16 rows x 128 cols = 512 float4, 2 per thread
#pragma unroll
        for (int u = 0; u < 2; u++) {
            int f = t + u*256;
            int row = f >> 5, c4 = f & 31;
            float4 bv;
            if (COLMAP == 0) {
                bv = *(const float4*)(B + (size_t)(k0 + row)*N + bn + c4*4);
            } else {
                int n0 = bn + c4*4;
                const float* bp = B + (size_t)(n0 >> 6)*((size_t)K*64) + (size_t)(k0 + row)*64 + (n0 & 63);
                bv = *(const float4*)bp;
            }
            *(float4*)&Bs[row][c4*4] = bv;
        }
        __syncthreads();
#pragma unroll
        for (int kk = 0; kk < 16; kk++) {
            float a[8], bb[8];
            *(float4*)&a[0]  = *(const float4*)&As[kk][ty*8];
            *(float4*)&a[4]  = *(const float4*)&As[kk][ty*8+4];
            *(float4*)&bb[0] = *(const float4*)&Bs[kk][tx*8];
            *(float4*)&bb[4] = *(const float4*)&Bs[kk][tx*8+4];
#pragma unroll
            for (int i = 0; i < 8; i++)
#pragma unroll
                for (int j = 0; j < 8; j++)
                    acc[i][j] = fmaf(a[i], bb[j], acc[i][j]);
        }
        __syncthreads();
    }

    // epilogue
#pragma unroll
    for (int i = 0; i < 8; i++) {
        int m = bm + ty*8 + i;
        float* crow = C + (size_t)m * N;
        const float* rrow = ADDRES ? (res + (size_t)m * N) : nullptr;
#pragma unroll
        for (int j = 0; j < 8; j++) {
            int n = bn + tx*8 + j;
            float v = acc[i][j] + bias[n];
            if (RELU)  v = fmaxf(v, 0.f);
            if (ADDRES) v += rrow[n];
            crow[n] = v;
        }
    }
}

// ---------------- Flash attention (fp32, causal, online softmax) ----------------
// grid: (SEQ/64, BATCH*N_HEADS), 64 threads; each thread owns one q row.
__global__ void attn_kernel(const float* __restrict__ Q, const float* __restrict__ K,
                            const float* __restrict__ V, float* __restrict__ Z) {
    __shared__ float Ks[32][64];
    __shared__ float Vs[32][64];
    int bh = blockIdx.y;
    int b  = bh / N_HEADS;
    int h  = bh % N_HEADS;
    int qi = blockIdx.x * 64 + threadIdx.x;
    int tok = b * SEQ + qi;

    float q[64];
    const float* qp = Q + (size_t)tok * D_MODEL + h * D_HEAD;
#pragma unroll
    for (int d = 0; d < 64; d++) q[d] = qp[d] * 0.125f;   // 1/sqrt(64)

    float m = -INFINITY, l = 0.f;
    float acc[64];
#pragma unroll
    for (int d = 0; d < 64; d++) acc[d] = 0.f;

    int ntiles = (blockIdx.x * 64 + 64 + 31) / 32;  // uniform per block
    for (int tt = 0; tt < ntiles; tt++) {
        int kv0 = tt * 32;
        __syncthreads();
        // cooperative load K/V tiles: 32 rows x 64 cols = 512 float4 each
        for (int f = threadIdx.x; f < 512; f += 64) {
            int r = f >> 4, c4 = f & 15;
            size_t goff = (size_t)(b*SEQ + kv0 + r) * D_MODEL + h * D_HEAD + c4*4;
            *(float4*)&Ks[r][c4*4] = *(const float4*)(K + goff);
            *(float4*)&Vs[r][c4*4] = *(const float4*)(V + goff);
        }
        __syncthreads();
        int jmax = qi - kv0 + 1;
        if (jmax > 32) jmax = 32;
        for (int j = 0; j < jmax; j++) {
            float s = 0.f;
#pragma unroll
            for (int d4 = 0; d4 < 16; d4++) {
                float4 kk = *(const float4*)&Ks[j][d4*4];
                s = fmaf(q[d4*4+0], kk.x, s);
                s = fmaf(q[d4*4+1], kk.y, s);
                s = fmaf(q[d4*4+2], kk.z, s);
                s = fmaf(q[d4*4+3], kk.w, s);
            }
            float mnew = fmaxf(m, s);
            float fac  = __expf(m - mnew);
            float p    = __expf(s - mnew);
            l = l * fac + p;
#pragma unroll
            for (int d4 = 0; d4 < 16; d4++) {
                float4 vv = *(const float4*)&Vs[j][d4*4];
                acc[d4*4+0] = fmaf(acc[d4*4+0], fac, p * vv.x);
                acc[d4*4+1] = fmaf(acc[d4*4+1], fac, p * vv.y);
                acc[d4*4+2] = fmaf(acc[d4*4+2], fac, p * vv.z);
                acc[d4*4+3] = fmaf(acc[d4*4+3], fac, p * vv.w);
            }
            m = mnew;
        }
    }
    float inv = 1.f / l;
    float* zp = Z + (size_t)tok * D_MODEL + h * D_HEAD;
#pragma unroll
    for (int d = 0; d < 64; d++) zp[d] = acc[d] * inv;
}

// ---------------- launch ----------------
extern "C" void kernel_launch(void* const* d_in, const int* in_sizes, int n_in,
                              void* d_out, int out_size) {
    const float* resid_pre = (const float*)d_in[0];
    const float* ln1_w = (const float*)d_in[1];
    const float* ln1_b = (const float*)d_in[2];
    const float* W_Q   = (const float*)d_in[3];
    const float* b_Q   = (const float*)d_in[4];
    const float* W_K   = (const float*)d_in[5];
    const float* b_K   = (const float*)d_in[6];
    const float* W_V   = (const float*)d_in[7];
    const float* b_V   = (const float*)d_in[8];
    const float* W_O   = (const float*)d_in[9];
    const float* b_O   = (const float*)d_in[10];
    const float* ln2_w = (const float*)d_in[11];
    const float* ln2_b = (const float*)d_in[12];
    const float* W_in  = (const float*)d_in[13];
    const float* b_in  = (const float*)d_in[14];
    const float* W_out = (const float*)d_in[15];
    const float* b_out = (const float*)d_in[16];
    float* out = (float*)d_out;

    float *p_ln1, *p_q, *p_k, *p_v, *p_z, *p_rmid, *p_ln2, *p_mlp;
    cudaGetSymbolAddress((void**)&p_ln1,  g_ln1);
    cudaGetSymbolAddress((void**)&p_q,    g_q);
    cudaGetSymbolAddress((void**)&p_k,    g_k);
    cudaGetSymbolAddress((void**)&p_v,    g_v);
    cudaGetSymbolAddress((void**)&p_z,    g_z);
    cudaGetSymbolAddress((void**)&p_rmid, g_rmid);
    cudaGetSymbolAddress((void**)&p_ln2,  g_ln2);
    cudaGetSymbolAddress((void**)&p_mlp,  g_mlp);

    // 1) LN1
    ln_kernel<<<NTOK, 256>>>(resid_pre, ln1_w, ln1_b, p_ln1);

    // 2) QKV projections (weights are [h, d, k] -> COLMAP 1)
    dim3 gProj(D_MODEL/128, NTOK/128);
    gemm128<1,false,false><<<gProj, 256>>>(p_ln1, W_Q, b_Q, nullptr, p_q, NTOK, D_MODEL, D_MODEL);
    gemm128<1,false,false><<<gProj, 256>>>(p_ln1, W_K, b_K, nullptr, p_k, NTOK, D_MODEL, D_MODEL);
    gemm128<1,false,false><<<gProj, 256>>>(p_ln1, W_V, b_V, nullptr, p_v, NTOK, D_MODEL, D_MODEL);

    // 3) attention
    attn_kernel<<<dim3(SEQ/64, BATCH*N_HEADS), 64>>>(p_q, p_k, p_v, p_z);

    // 4) O projection + residual (W_O [h,k,d] is contiguous [1024,1024] row-major)
    gemm128<0,false,true><<<gProj, 256>>>(p_z, W_O, b_O, resid_pre, p_rmid, NTOK, D_MODEL, D_MODEL);

    // 5) LN2
    ln_kernel<<<NTOK, 256>>>(p_rmid, ln2_w, ln2_b, p_ln2);

    // 6) MLP in + ReLU
    dim3 gMlp1(D_MLP/128, NTOK/128);
    gemm128<0,true,false><<<gMlp1, 256>>>(p_ln2, W_in, b_in, nullptr, p_mlp, NTOK, D_MLP, D_MODEL);

    // 7) MLP out + residual -> output
    gemm128<0,false,true><<<gProj, 256>>>(p_mlp, W_out, b_out, p_rmid, out, NTOK, D_MODEL, D_MLP);
}

// round 5
// speedup vs baseline: 1.5257x; 1.5257x over previous
#include <cuda_runtime.h>
#include <cuda_bf16.h>
#include <math.h>
#include <stdint.h>

#define D_MODEL 1024
#define N_HEADS 16
#define D_HEAD  64
#define D_MLP   4096
#define BATCH   2
#define SEQ     2048
#define NTOK    (BATCH*SEQ)   // 4096
#define LN_EPS  1e-5f

// ---------------------------------------------------------------------------
// scratch (static device globals; no allocation)
// ---------------------------------------------------------------------------
__device__ __nv_bfloat16 g_ln1h[NTOK*D_MODEL];
__device__ __nv_bfloat16 g_ln1l[NTOK*D_MODEL];
__device__ float         g_q  [NTOK*D_MODEL];
__device__ float         g_k  [NTOK*D_MODEL];
__device__ float         g_v  [NTOK*D_MODEL];
__device__ __nv_bfloat16 g_zh [NTOK*D_MODEL];
__device__ __nv_bfloat16 g_zl [NTOK*D_MODEL];
__device__ float         g_rmid[NTOK*D_MODEL];
__device__ __nv_bfloat16 g_ln2h[NTOK*D_MODEL];
__device__ __nv_bfloat16 g_ln2l[NTOK*D_MODEL];
__device__ __nv_bfloat16 g_mlph[(size_t)NTOK*D_MLP];
__device__ __nv_bfloat16 g_mlpl[(size_t)NTOK*D_MLP];
// transposed+split weights ([N,K] row-major, k-contiguous)
__device__ __nv_bfloat16 g_wqh[D_MODEL*D_MODEL], g_wql[D_MODEL*D_MODEL];
__device__ __nv_bfloat16 g_wkh[D_MODEL*D_MODEL], g_wkl[D_MODEL*D_MODEL];
__device__ __nv_bfloat16 g_wvh[D_MODEL*D_MODEL], g_wvl[D_MODEL*D_MODEL];
__device__ __nv_bfloat16 g_woh[D_MODEL*D_MODEL], g_wol[D_MODEL*D_MODEL];
__device__ __nv_bfloat16 g_winh[(size_t)D_MODEL*D_MLP], g_winl[(size_t)D_MODEL*D_MLP];
__device__ __nv_bfloat16 g_wouth[(size_t)D_MLP*D_MODEL], g_woutl[(size_t)D_MLP*D_MODEL];

// ---------------------------------------------------------------------------
// helpers
// ---------------------------------------------------------------------------
__device__ __forceinline__ uint32_t smem_to_u32(const void* p) {
    uint32_t a;
    asm("{ .reg .u64 t; cvta.to.shared.u64 t, %1; cvt.u32.u64 %0, t; }" : "=r"(a) : "l"(p));
    return a;
}
__device__ __forceinline__ void cp16(uint32_t s, const void* g) {
    asm volatile("cp.async.cg.shared.global [%0], [%1], 16;" :: "r"(s), "l"(g));
}
__device__ __forceinline__ void ldmx4(uint32_t* r, uint32_t addr) {
    asm volatile("ldmatrix.sync.aligned.m8n8.x4.shared.b16 {%0,%1,%2,%3}, [%4];"
        : "=r"(r[0]), "=r"(r[1]), "=r"(r[2]), "=r"(r[3]) : "r"(addr));
}
__device__ __forceinline__ void mma16816(float* d, const uint32_t* a, uint32_t b0, uint32_t b1) {
    asm volatile("mma.sync.aligned.m16n8k16.row.col.f32.bf16.bf16.f32 "
        "{%0,%1,%2,%3}, {%4,%5,%6,%7}, {%8,%9}, {%0,%1,%2,%3};"
        : "+f"(d[0]), "+f"(d[1]), "+f"(d[2]), "+f"(d[3])
        : "r"(a[0]), "r"(a[1]), "r"(a[2]), "r"(a[3]), "r"(b0), "r"(b1));
}
__device__ __forceinline__ void split2(float x, __nv_bfloat16& h, __nv_bfloat16& l) {
    h = __float2bfloat16(x);
    l = __float2bfloat16(x - __bfloat162float(h));
}

// ---------------------------------------------------------------------------
// weight transpose + split: src is batch x [K,N] fp32 row-major
// out rows: b*N + n, cols: k  (bf16 hi/lo, [batch*N, K] row-major)
// ---------------------------------------------------------------------------
__global__ void transpose_split_kernel(const float* __restrict__ src,
                                       __nv_bfloat16* __restrict__ hi,
                                       __nv_bfloat16* __restrict__ lo,
                                       int K, int N) {
    __shared__ float t[32][33];
    int b  = blockIdx.z;
    int n0 = blockIdx.x * 32, k0 = blockIdx.y * 32;
    const float* s = src + (size_t)b * K * N;
#pragma unroll
    for (int i = 0; i < 4; i++)
        t[threadIdx.y + i*8][threadIdx.x] = s[(size_t)(k0 + threadIdx.y + i*8) * N + n0 + threadIdx.x];
    __syncthreads();
#pragma unroll
    for (int i = 0; i < 4; i++) {
        float v = t[threadIdx.x][threadIdx.y + i*8];
        size_t o = (size_t)(b * N + n0 + threadIdx.y + i*8) * K + k0 + threadIdx.x;
        __nv_bfloat16 h, l; split2(v, h, l);
        hi[o] = h; lo[o] = l;
    }
}

// ---------------------------------------------------------------------------
// LayerNorm -> split bf16 hi/lo
// ---------------------------------------------------------------------------
__global__ void ln_split_kernel(const float* __restrict__ x, const float* __restrict__ w,
                                const float* __restrict__ b,
                                __nv_bfloat16* __restrict__ oh, __nv_bfloat16* __restrict__ ol) {
    int row = blockIdx.x;
    const float* xr = x + (size_t)row * D_MODEL;
    float vals[4];
    float s = 0.f, s2 = 0.f;
#pragma unroll
    for (int i = 0; i < 4; i++) {
        float v = xr[threadIdx.x + i*256];
        vals[i] = v; s += v; s2 += v*v;
    }
#pragma unroll
    for (int o = 16; o > 0; o >>= 1) {
        s  += __shfl_xor_sync(0xFFFFFFFFu, s,  o);
        s2 += __shfl_xor_sync(0xFFFFFFFFu, s2, o);
    }
    __shared__ float sh[2][8];
    int wid = threadIdx.x >> 5, lid = threadIdx.x & 31;
    if (lid == 0) { sh[0][wid] = s; sh[1][wid] = s2; }
    __syncthreads();
    s = 0.f; s2 = 0.f;
#pragma unroll
    for (int i = 0; i < 8; i++) { s += sh[0][i]; s2 += sh[1][i]; }
    float mean = s * (1.f/(float)D_MODEL);
    float var  = s2 * (1.f/(float)D_MODEL) - mean*mean;
    float rstd = rsqrtf(var + LN_EPS);
#pragma unroll
    for (int i = 0; i < 4; i++) {
        int c = threadIdx.x + i*256;
        float v = (vals[i] - mean) * rstd * w[c] + b[c];
        __nv_bfloat16 h, l; split2(v, h, l);
        oh[(size_t)row * D_MODEL + c] = h;
        ol[(size_t)row * D_MODEL + c] = l;
    }
}

// ---------------------------------------------------------------------------
// HMMA (mma.sync bf16) GEMM: C[M,N] = (Ah+Al)[M,K] @ (Bh+Bl)^T   (B stored [N,K])
// 3 products: Ah*Bh + Ah*Bl + Al*Bh, fp32 accumulators.
// CTA tile 128x128, BK=32, 256 threads (8 warps, 2x4 warp grid, 64x32/warp).
// Smem tiles padded to 80B rows (conflict-free ldmatrix), cp.async double buffer.
// ---------------------------------------------------------------------------
#define TILE_B   10240               // 128 rows * 80 bytes
#define STAGE_B  (4*TILE_B)          // Ah, Al, Bh, Bl
#define GEMM_SMEM (2*STAGE_B)        // 81920

template<bool RELU, bool ADDRES, bool SPLIT>
__global__ void __launch_bounds__(256, 1) gemm_mma(
    const __nv_bfloat16* __restrict__ Ah, const __nv_bfloat16* __restrict__ Al,
    const __nv_bfloat16* __restrict__ Bh, const __nv_bfloat16* __restrict__ Bl,
    const float* __restrict__ bias, const float* __restrict__ res,
    float* __restrict__ C, __nv_bfloat16* __restrict__ Ch, __nv_bfloat16* __restrict__ Cl,
    int M, int N, int K)
{
    extern __shared__ __align__(128) char smem[];
    const uint32_t sbase = smem_to_u32(smem);
    const int tid  = threadIdx.x;
    const int lane = tid & 31;
    const int wid  = tid >> 5;
    const int wm   = wid >> 2;           // 0..1  -> m offset 64*wm
    const int wn   = wid & 3;            // 0..3  -> n offset 32*wn
    const int bm   = blockIdx.y * 128;
    const int bn   = blockIdx.x * 128;

    float acc[4][4][4];
#pragma unroll
    for (int i = 0; i < 4; i++)
#pragma unroll
        for (int j = 0; j < 4; j++)
#pragma unroll
            for (int q = 0; q < 4; q++) acc[i][j][q] = 0.f;

    const int nk = K >> 5;   // BK = 32

    // --- stage loader: 4 tiles x 512 16B-chunks, 2 chunks/thread/tile
    auto load_stage = [&](int kt, int buf) {
        const int k0 = kt << 5;
        const uint32_t sb0 = sbase + buf * STAGE_B;
#pragma unroll
        for (int u = 0; u < 2; u++) {
            int f   = tid + u * 256;
            int row = f >> 2, c = f & 3;
            uint32_t soff = (uint32_t)(row * 80 + c * 16);
            size_t gA = (size_t)(bm + row) * K + k0 + c * 8;
            size_t gB = (size_t)(bn + row) * K + k0 + c * 8;
            cp16(sb0 + 0*TILE_B + soff, Ah + gA);
            cp16(sb0 + 1*TILE_B + soff, Al + gA);
            cp16(sb0 + 2*TILE_B + soff, Bh + gB);
            cp16(sb0 + 3*TILE_B + soff, Bl + gB);
        }
    };

    // per-warp ldmatrix base offsets (within a tile)
    const uint32_t aRowOff = (uint32_t)((wm*64 + (lane & 15)) * 80 + (lane >> 4) * 16);
    const uint32_t bRowOff = (uint32_t)((wn*32 + (lane & 15)) * 80 + (lane >> 4) * 16);

    load_stage(0, 0);
    asm volatile("cp.async.commit_group;");

    for (int kt = 0; kt < nk; kt++) {
        if (kt + 1 < nk) {
            load_stage(kt + 1, (kt + 1) & 1);
            asm volatile("cp.async.commit_group;");
            asm volatile("cp.async.wait_group 1;");
        } else {
            asm volatile("cp.async.wait_group 0;");
        }
        __syncthreads();

        const uint32_t sb0 = sbase + (kt & 1) * STAGE_B;
#pragma unroll
        for (int ks = 0; ks < 2; ks++) {
            const uint32_t koff = ks * 32;   // bytes: 16 bf16
            uint32_t a[4][4], bh[2][4], bl[2][4];
#pragma unroll
            for (int i = 0; i < 4; i++)
                ldmx4(a[i], sb0 + 0*TILE_B + aRowOff + (uint32_t)(i*16*80) + koff);
#pragma unroll
            for (int j = 0; j < 2; j++) {
                ldmx4(bh[j], sb0 + 2*TILE_B + bRowOff + (uint32_t)(j*16*80) + koff);
                ldmx4(bl[j], sb0 + 3*TILE_B + bRowOff + (uint32_t)(j*16*80) + koff);
            }
            // P1: Ah * Bh
#pragma unroll
            for (int i = 0; i < 4; i++)
#pragma unroll
                for (int nb = 0; nb < 4; nb++) {
                    int j = nb >> 1, sel = nb & 1;
                    mma16816(acc[i][nb], a[i], bh[j][sel], bh[j][sel + 2]);
                }
            // P2: Ah * Bl
#pragma unroll
            for (int i = 0; i < 4; i++)
#pragma unroll
                for (int nb = 0; nb < 4; nb++) {
                    int j = nb >> 1, sel = nb & 1;
                    mma16816(acc[i][nb], a[i], bl[j][sel], bl[j][sel + 2]);
                }
            // reload A-lo into same regs, P3: Al * Bh
#pragma unroll
            for (int i = 0; i < 4; i++)
                ldmx4(a[i], sb0 + 1*TILE_B + aRowOff + (uint32_t)(i*16*80) + koff);
#pragma unroll
            for (int i = 0; i < 4; i++)
#pragma unroll
                for (int nb = 0; nb < 4; nb++) {
                    int j = nb >> 1, sel = nb & 1;
                    mma16816(acc[i][nb], a[i], bh[j][sel], bh[j][sel + 2]);
                }
        }
        __syncthreads();
    }

    // --- epilogue ---
    const int mrow = bm + wm*64 + (lane >> 2);
    const int ncol = bn + wn*32 + (lane & 3) * 2;
#pragma unroll
    for (int i = 0; i < 4; i++) {
#pragma unroll
        for (int jj = 0; jj < 4; jj++) {
            int r0 = mrow + i*16;
            int c  = ncol + jj*8;
            float2 bv = *(const float2*)(bias + c);
            float x0 = acc[i][jj][0] + bv.x;
            float x1 = acc[i][jj][1] + bv.y;
            float x2 = acc[i][jj][2] + bv.x;
            float x3 = acc[i][jj][3] + bv.y;
            if (RELU) {
                x0 = fmaxf(x0, 0.f); x1 = fmaxf(x1, 0.f);
                x2 = fmaxf(x2, 0.f); x3 = fmaxf(x3, 0.f);
            }
            if (ADDRES) {
                float2 rv0 = *(const float2*)(res + (size_t)r0 * N + c);
                float2 rv1 = *(const float2*)(res + (size_t)(r0+8) * N + c);
                x0 += rv0.x; x1 += rv0.y; x2 += rv1.x; x3 += rv1.y;
            }
            if (SPLIT) {
                __nv_bfloat16 h0,l0,h1,l1,h2,l2,h3,l3;
                split2(x0,h0,l0); split2(x1,h1,l1); split2(x2,h2,l2); split2(x3,h3,l3);
                *(__nv_bfloat162*)(Ch + (size_t)r0 * N + c)     = __nv_bfloat162(h0, h1);
                *(__nv_bfloat162*)(Ch + (size_t)(r0+8) * N + c) = __nv_bfloat162(h2, h3);
                *(__nv_bfloat162*)(Cl + (size_t)r0 * N + c)     = __nv_bfloat162(l0, l1);
                *(__nv_bfloat162*)(Cl + (size_t)(r0+8) * N + c) = __nv_bfloat162(l2, l3);
            } else {
                *(float2*)(C + (size_t)r0 * N + c)     = make_float2(x0, x1);
                *(float2*)(C + (size_t)(r0+8) * N + c) = make_float2(x2, x3);
            }
        }
    }
}

// ---------------------------------------------------------------------------
// Flash attention (fp32, causal, online softmax) -> split bf16 z
// ---------------------------------------------------------------------------
__global__ void attn_kernel(const float* __restrict__ Q, const float* __restrict__ K,
                            const float* __restrict__ V,
                            __nv_bfloat16* __restrict__ Zh, __nv_bfloat16* __restrict__ Zl) {
    __shared__ float Ks[32][64];
    __shared__ float Vs[32][64];
    int bh = blockIdx.y;
    int b  = bh / N_HEADS;
    int h  = bh % N_HEADS;
    int qi = blockIdx.x * 64 + threadIdx.x;
    int tok = b * SEQ + qi;

    float q[64];
    const float* qp = Q + (size_t)tok * D_MODEL + h * D_HEAD;
#pragma unroll
    for (int d = 0; d < 64; d++) q[d] = qp[d] * 0.125f;   // 1/sqrt(64)

    float m = -INFINITY, l = 0.f;
    float acc[64];
#pragma unroll
    for (int d = 0; d < 64; d++) acc[d] = 0.f;

    int ntiles = (blockIdx.x * 64 + 64 + 31) / 32;
    for (int tt = 0; tt < ntiles; tt++) {
        int kv0 = tt * 32;
        __syncthreads();
        for (int f = threadIdx.x; f < 512; f += 64) {
            int r = f >> 4, c4 = f & 15;
            size_t goff = (size_t)(b*SEQ + kv0 + r) * D_MODEL + h * D_HEAD + c4*4;
            *(float4*)&Ks[r][c4*4] = *(const float4*)(K + goff);
            *(float4*)&Vs[r][c4*4] = *(const float4*)(V + goff);
        }
        __syncthreads();
        int jmax = qi - kv0 + 1;
        if (jmax > 32) jmax = 32;
        for (int j = 0; j < jmax; j++) {
            float s = 0.f;
#pragma unroll
            for (int d4 = 0; d4 < 16; d4++) {
                float4 kk = *(const float4*)&Ks[j][d4*4];
                s = fmaf(q[d4*4+0], kk.x, s);
                s = fmaf(q[d4*4+1], kk.y, s);
                s = fmaf(q[d4*4+2], kk.z, s);
                s = fmaf(q[d4*4+3], kk.w, s);
            }
            float mnew = fmaxf(m, s);
            float fac  = __expf(m - mnew);
            float p    = __expf(s - mnew);
            l = l * fac + p;
#pragma unroll
            for (int d4 = 0; d4 < 16; d4++) {
                float4 vv = *(const float4*)&Vs[j][d4*4];
                acc[d4*4+0] = fmaf(acc[d4*4+0], fac, p * vv.x);
                acc[d4*4+1] = fmaf(acc[d4*4+1], fac, p * vv.y);
                acc[d4*4+2] = fmaf(acc[d4*4+2], fac, p * vv.z);
                acc[d4*4+3] = fmaf(acc[d4*4+3], fac, p * vv.w);
            }
            m = mnew;
        }
    }
    float inv = 1.f / l;
    size_t zoff = (size_t)tok * D_MODEL + h * D_HEAD;
#pragma unroll
    for (int d = 0; d < 64; d++) {
        __nv_bfloat16 hh, ll; split2(acc[d] * inv, hh, ll);
        Zh[zoff + d] = hh;
        Zl[zoff + d] = ll;
    }
}

// ---------------------------------------------------------------------------
// launch
// ---------------------------------------------------------------------------
extern "C" void kernel_launch(void* const* d_in, const int* in_sizes, int n_in,
                              void* d_out, int out_size) {
    const float* resid_pre = (const float*)d_in[0];
    const float* ln1_w = (const float*)d_in[1];
    const float* ln1_b = (const float*)d_in[2];
    const float* W_Q   = (const float*)d_in[3];
    const float* b_Q   = (const float*)d_in[4];
    const float* W_K   = (const float*)d_in[5];
    const float* b_K   = (const float*)d_in[6];
    const float* W_V   = (const float*)d_in[7];
    const float* b_V   = (const float*)d_in[8];
    const float* W_O   = (const float*)d_in[9];
    const float* b_O   = (const float*)d_in[10];
    const float* ln2_w = (const float*)d_in[11];
    const float* ln2_b = (const float*)d_in[12];
    const float* W_in  = (const float*)d_in[13];
    const float* b_in  = (const float*)d_in[14];
    const float* W_out = (const float*)d_in[15];
    const float* b_out = (const float*)d_in[16];
    float* out = (float*)d_out;

    __nv_bfloat16 *p_ln1h, *p_ln1l, *p_zh, *p_zl, *p_ln2h, *p_ln2l, *p_mlph, *p_mlpl;
    __nv_bfloat16 *p_wqh, *p_wql, *p_wkh, *p_wkl, *p_wvh, *p_wvl, *p_woh, *p_wol;
    __nv_bfloat16 *p_winh, *p_winl, *p_wouth, *p_woutl;
    float *p_q, *p_k, *p_v, *p_rmid;

    cudaGetSymbolAddress((void**)&p_ln1h, g_ln1h);  cudaGetSymbolAddress((void**)&p_ln1l, g_ln1l);
    cudaGetSymbolAddress((void**)&p_q, g_q);        cudaGetSymbolAddress((void**)&p_k, g_k);
    cudaGetSymbolAddress((void**)&p_v, g_v);
    cudaGetSymbolAddress((void**)&p_zh, g_zh);      cudaGetSymbolAddress((void**)&p_zl, g_zl);
    cudaGetSymbolAddress((void**)&p_rmid, g_rmid);
    cudaGetSymbolAddress((void**)&p_ln2h, g_ln2h);  cudaGetSymbolAddress((void**)&p_ln2l, g_ln2l);
    cudaGetSymbolAddress((void**)&p_mlph, g_mlph);  cudaGetSymbolAddress((void**)&p_mlpl, g_mlpl);
    cudaGetSymbolAddress((void**)&p_wqh, g_wqh);    cudaGetSymbolAddress((void**)&p_wql, g_wql);
    cudaGetSymbolAddress((void**)&p_wkh, g_wkh);    cudaGetSymbolAddress((void**)&p_wkl, g_wkl);
    cudaGetSymbolAddress((void**)&p_wvh, g_wvh);    cudaGetSymbolAddress((void**)&p_wvl, g_wvl);
    cudaGetSymbolAddress((void**)&p_woh, g_woh);    cudaGetSymbolAddress((void**)&p_wol, g_wol);
    cudaGetSymbolAddress((void**)&p_winh, g_winh);  cudaGetSymbolAddress((void**)&p_winl, g_winl);
    cudaGetSymbolAddress((void**)&p_wouth, g_wouth);cudaGetSymbolAddress((void**)&p_woutl, g_woutl);

    cudaFuncSetAttribute(gemm_mma<false,false,false>, cudaFuncAttributeMaxDynamicSharedMemorySize, GEMM_SMEM);
    cudaFuncSetAttribute(gemm_mma<false,true ,false>, cudaFuncAttributeMaxDynamicSharedMemorySize, GEMM_SMEM);
    cudaFuncSetAttribute(gemm_mma<true ,false,true >, cudaFuncAttributeMaxDynamicSharedMemorySize, GEMM_SMEM);

    dim3 tb(32, 8);
    // weight prep: transpose + split to [N,K] bf16 hi/lo
    transpose_split_kernel<<<dim3(2, 32, 16),  tb>>>(W_Q,   p_wqh,   p_wql,   D_MODEL, D_HEAD);
    transpose_split_kernel<<<dim3(2, 32, 16),  tb>>>(W_K,   p_wkh,   p_wkl,   D_MODEL, D_HEAD);
    transpose_split_kernel<<<dim3(2, 32, 16),  tb>>>(W_V,   p_wvh,   p_wvl,   D_MODEL, D_HEAD);
    transpose_split_kernel<<<dim3(32, 32, 1),  tb>>>(W_O,   p_woh,   p_wol,   D_MODEL, D_MODEL);
    transpose_split_kernel<<<dim3(128, 32, 1), tb>>>(W_in,  p_winh,  p_winl,  D_MODEL, D_MLP);
    transpose_split_kernel<<<dim3(32, 128, 1), tb>>>(W_out, p_wouth, p_woutl, D_MLP,   D_MODEL);

    // 1) LN1 -> split
    ln_split_kernel<<<NTOK, 256>>>(resid_pre, ln1_w, ln1_b, p_ln1h, p_ln1l);

    // 2) QKV projections (fp32 out)
    dim3 gProj(D_MODEL/128, NTOK/128);
    gemm_mma<false,false,false><<<gProj, 256, GEMM_SMEM>>>(p_ln1h, p_ln1l, p_wqh, p_wql, b_Q, nullptr, p_q, nullptr, nullptr, NTOK, D_MODEL, D_MODEL);
    gemm_mma<false,false,false><<<gProj, 256, GEMM_SMEM>>>(p_ln1h, p_ln1l, p_wkh, p_wkl, b_K, nullptr, p_k, nullptr, nullptr, NTOK, D_MODEL, D_MODEL);
    gemm_mma<false,false,false><<<gProj, 256, GEMM_SMEM>>>(p_ln1h, p_ln1l, p_wvh, p_wvl, b_V, nullptr, p_v, nullptr, nullptr, NTOK, D_MODEL, D_MODEL);

    // 3) attention -> split z
    attn_kernel<<<dim3(SEQ/64, BATCH*N_HEADS), 64>>>(p_q, p_k, p_v, p_zh, p_zl);

    // 4) O projection + residual -> rmid (fp32)
    gemm_mma<false,true,false><<<gProj, 256, GEMM_SMEM>>>(p_zh, p_zl, p_woh, p_wol, b_O, resid_pre, p_rmid, nullptr, nullptr, NTOK, D_MODEL, D_MODEL);

    // 5) LN2 -> split
    ln_split_kernel<<<NTOK, 256>>>(p_rmid, ln2_w, ln2_b, p_ln2h, p_ln2l);

    // 6) MLP in + ReLU -> split mlp
    dim3 gMlp1(D_MLP/128, NTOK/128);
    gemm_mma<true,false,true><<<gMlp1, 256, GEMM_SMEM>>>(p_ln2h, p_ln2l, p_winh, p_winl, b_in, nullptr, nullptr, p_mlph, p_mlpl, NTOK, D_MLP, D_MODEL);

    // 7) MLP out + residual -> output (fp32)
    gemm_mma<false,true,false><<<gProj, 256, GEMM_SMEM>>>(p_mlph, p_mlpl, p_wouth, p_woutl, b_out, p_rmid, out, nullptr, nullptr, NTOK, D_MODEL, D_MLP);
}

// round 6
// speedup vs baseline: 2.2877x; 1.4995x over previous
#include <cuda_runtime.h>
#include <cuda_fp16.h>
#include <math.h>
#include <stdint.h>

#define D_MODEL 1024
#define N_HEADS 16
#define D_HEAD  64
#define D_MLP   4096
#define BATCH   2
#define SEQ     2048
#define NTOK    (BATCH*SEQ)   // 4096
#define LN_EPS  1e-5f

// ---------------------------------------------------------------------------
// scratch (static device globals; no allocation)
// ---------------------------------------------------------------------------
__device__ __half g_ln1[NTOK*D_MODEL];
__device__ float  g_q  [NTOK*D_MODEL];
__device__ float  g_k  [NTOK*D_MODEL];
__device__ float  g_v  [NTOK*D_MODEL];
__device__ __half g_z  [NTOK*D_MODEL];
__device__ float  g_rmid[NTOK*D_MODEL];
__device__ __half g_ln2[NTOK*D_MODEL];
__device__ __half g_mlp[(size_t)NTOK*D_MLP];
// transposed fp16 weights ([N,K] row-major, k-contiguous)
__device__ __half g_wqkv[3*D_MODEL*D_MODEL];     // rows 0..1023 Q, 1024..2047 K, 2048..3071 V
__device__ __half g_wo  [D_MODEL*D_MODEL];
__device__ __half g_win [(size_t)D_MLP*D_MODEL];
__device__ __half g_wout[(size_t)D_MODEL*D_MLP];

// ---------------------------------------------------------------------------
// helpers
// ---------------------------------------------------------------------------
__device__ __forceinline__ uint32_t smem_to_u32(const void* p) {
    uint32_t a;
    asm("{ .reg .u64 t; cvta.to.shared.u64 t, %1; cvt.u32.u64 %0, t; }" : "=r"(a) : "l"(p));
    return a;
}
__device__ __forceinline__ void cp16(uint32_t s, const void* g) {
    asm volatile("cp.async.cg.shared.global [%0], [%1], 16;" :: "r"(s), "l"(g));
}
__device__ __forceinline__ void ldmx4(uint32_t* r, uint32_t addr) {
    asm volatile("ldmatrix.sync.aligned.m8n8.x4.shared.b16 {%0,%1,%2,%3}, [%4];"
        : "=r"(r[0]), "=r"(r[1]), "=r"(r[2]), "=r"(r[3]) : "r"(addr));
}
__device__ __forceinline__ void mma16816(float* d, const uint32_t* a, uint32_t b0, uint32_t b1) {
    asm volatile("mma.sync.aligned.m16n8k16.row.col.f32.f16.f16.f32 "
        "{%0,%1,%2,%3}, {%4,%5,%6,%7}, {%8,%9}, {%0,%1,%2,%3};"
        : "+f"(d[0]), "+f"(d[1]), "+f"(d[2]), "+f"(d[3])
        : "r"(a[0]), "r"(a[1]), "r"(a[2]), "r"(a[3]), "r"(b0), "r"(b1));
}

// ---------------------------------------------------------------------------
// weight transpose: src is batch x [K,N] fp32 row-major
// out rows: b*N + n, cols: k  (fp16, [batch*N, K] row-major)
// ---------------------------------------------------------------------------
__global__ void transpose_h_kernel(const float* __restrict__ src,
                                   __half* __restrict__ dst,
                                   int K, int N) {
    __shared__ float t[32][33];
    int b  = blockIdx.z;
    int n0 = blockIdx.x * 32, k0 = blockIdx.y * 32;
    const float* s = src + (size_t)b * K * N;
#pragma unroll
    for (int i = 0; i < 4; i++)
        t[threadIdx.y + i*8][threadIdx.x] = s[(size_t)(k0 + threadIdx.y + i*8) * N + n0 + threadIdx.x];
    __syncthreads();
#pragma unroll
    for (int i = 0; i < 4; i++) {
        float v = t[threadIdx.x][threadIdx.y + i*8];
        size_t o = (size_t)(b * N + n0 + threadIdx.y + i*8) * K + k0 + threadIdx.x;
        dst[o] = __float2half_rn(v);
    }
}

// ---------------------------------------------------------------------------
// LayerNorm -> fp16
// ---------------------------------------------------------------------------
__global__ void ln_h_kernel(const float* __restrict__ x, const float* __restrict__ w,
                            const float* __restrict__ b, __half* __restrict__ o) {
    int row = blockIdx.x;
    const float* xr = x + (size_t)row * D_MODEL;
    float vals[4];
    float s = 0.f, s2 = 0.f;
#pragma unroll
    for (int i = 0; i < 4; i++) {
        float v = xr[threadIdx.x + i*256];
        vals[i] = v; s += v; s2 += v*v;
    }
#pragma unroll
    for (int off = 16; off > 0; off >>= 1) {
        s  += __shfl_xor_sync(0xFFFFFFFFu, s,  off);
        s2 += __shfl_xor_sync(0xFFFFFFFFu, s2, off);
    }
    __shared__ float sh[2][8];
    int wid = threadIdx.x >> 5, lid = threadIdx.x & 31;
    if (lid == 0) { sh[0][wid] = s; sh[1][wid] = s2; }
    __syncthreads();
    s = 0.f; s2 = 0.f;
#pragma unroll
    for (int i = 0; i < 8; i++) { s += sh[0][i]; s2 += sh[1][i]; }
    float mean = s * (1.f/(float)D_MODEL);
    float var  = s2 * (1.f/(float)D_MODEL) - mean*mean;
    float rstd = rsqrtf(var + LN_EPS);
#pragma unroll
    for (int i = 0; i < 4; i++) {
        int c = threadIdx.x + i*256;
        float v = (vals[i] - mean) * rstd * w[c] + b[c];
        o[(size_t)row * D_MODEL + c] = __float2half_rn(v);
    }
}

// ---------------------------------------------------------------------------
// fp16 HMMA GEMM: C[M,N] = A[M,K] @ B^T  (B stored [N,K] fp16)
// CTA tile 128x128, BK=32, 256 threads (8 warps, 2x4 grid, 64x32/warp),
// cp.async double buffer, 2 CTAs/SM.
// MODE 0: fp32 C = acc + bias
// MODE 1: fp32 C = acc + bias + res
// MODE 2: fp16 Ch = relu(acc + bias)
// SEG: select output/bias segment by bn>>10 (fused QKV; ldc=1024)
// ---------------------------------------------------------------------------
#define TILE_B    10240              // 128 rows * 80 bytes
#define STAGE_B   (2*TILE_B)         // A + B tiles
#define GEMM_SMEM (2*STAGE_B)        // 40960 (double buffered)

template<int MODE, bool SEG>
__global__ void __launch_bounds__(256, 2) gemm_h(
    const __half* __restrict__ A, const __half* __restrict__ B,
    const float* __restrict__ b0, const float* __restrict__ b1, const float* __restrict__ b2,
    const float* __restrict__ res,
    float* __restrict__ C0, float* __restrict__ C1, float* __restrict__ C2,
    __half* __restrict__ Ch,
    int M, int N, int K)
{
    extern __shared__ __align__(128) char smem[];
    const uint32_t sbase = smem_to_u32(smem);
    const int tid  = threadIdx.x;
    const int lane = tid & 31;
    const int wid  = tid >> 5;
    const int wm   = wid >> 2;           // 0..1  -> m offset 64*wm
    const int wn   = wid & 3;            // 0..3  -> n offset 32*wn
    const int bm   = blockIdx.y * 128;
    const int bn   = blockIdx.x * 128;

    const float* bias = b0;
    float* C = C0;
    int bnl = bn, ldc = N;
    if (SEG) {
        int sg = bn >> 10;
        bias = (sg == 0) ? b0 : (sg == 1) ? b1 : b2;
        C    = (sg == 0) ? C0 : (sg == 1) ? C1 : C2;
        bnl  = bn & 1023;
        ldc  = 1024;
    }

    float acc[4][4][4];
#pragma unroll
    for (int i = 0; i < 4; i++)
#pragma unroll
        for (int j = 0; j < 4; j++)
#pragma unroll
            for (int q = 0; q < 4; q++) acc[i][j][q] = 0.f;

    const int nk = K >> 5;   // BK = 32

    auto load_stage = [&](int kt, int buf) {
        const int k0 = kt << 5;
        const uint32_t sb0 = sbase + buf * STAGE_B;
        // 2 tiles x 512 chunks of 16B; 2 chunks/thread/tile
#pragma unroll
        for (int u = 0; u < 2; u++) {
            int f   = tid + u * 256;
            int row = f >> 2, c = f & 3;
            uint32_t soff = (uint32_t)(row * 80 + c * 16);
            cp16(sb0 + 0*TILE_B + soff, A + (size_t)(bm + row) * K + k0 + c * 8);
            cp16(sb0 + 1*TILE_B + soff, B + (size_t)(bn + row) * K + k0 + c * 8);
        }
    };

    const uint32_t aRowOff = (uint32_t)((wm*64 + (lane & 15)) * 80 + (lane >> 4) * 16);
    const uint32_t bRowOff = (uint32_t)((wn*32 + (lane & 15)) * 80 + (lane >> 4) * 16);

    load_stage(0, 0);
    asm volatile("cp.async.commit_group;");

    for (int kt = 0; kt < nk; kt++) {
        if (kt + 1 < nk) {
            load_stage(kt + 1, (kt + 1) & 1);
            asm volatile("cp.async.commit_group;");
            asm volatile("cp.async.wait_group 1;");
        } else {
            asm volatile("cp.async.wait_group 0;");
        }
        __syncthreads();

        const uint32_t sb0 = sbase + (kt & 1) * STAGE_B;
#pragma unroll
        for (int ks = 0; ks < 2; ks++) {
            const uint32_t koff = ks * 32;   // 16 halves = 32 bytes
            uint32_t a[4][4], bb[2][4];
#pragma unroll
            for (int i = 0; i < 4; i++)
                ldmx4(a[i], sb0 + 0*TILE_B + aRowOff + (uint32_t)(i*16*80) + koff);
#pragma unroll
            for (int j = 0; j < 2; j++)
                ldmx4(bb[j], sb0 + 1*TILE_B + bRowOff + (uint32_t)(j*16*80) + koff);
#pragma unroll
            for (int i = 0; i < 4; i++)
#pragma unroll
                for (int nb = 0; nb < 4; nb++) {
                    int j = nb >> 1, sel = nb & 1;
                    mma16816(acc[i][nb], a[i], bb[j][sel], bb[j][sel + 2]);
                }
        }
        __syncthreads();
    }

    // --- epilogue ---
    const int mrow = bm + wm*64 + (lane >> 2);
    const int ncol = bnl + wn*32 + (lane & 3) * 2;
#pragma unroll
    for (int i = 0; i < 4; i++) {
#pragma unroll
        for (int jj = 0; jj < 4; jj++) {
            int r0 = mrow + i*16;
            int c  = ncol + jj*8;
            float2 bv = *(const float2*)(bias + c);
            float x0 = acc[i][jj][0] + bv.x;
            float x1 = acc[i][jj][1] + bv.y;
            float x2 = acc[i][jj][2] + bv.x;
            float x3 = acc[i][jj][3] + bv.y;
            if (MODE == 2) {
                x0 = fmaxf(x0, 0.f); x1 = fmaxf(x1, 0.f);
                x2 = fmaxf(x2, 0.f); x3 = fmaxf(x3, 0.f);
                *(__half2*)(Ch + (size_t)r0 * ldc + c)     = __floats2half2_rn(x0, x1);
                *(__half2*)(Ch + (size_t)(r0+8) * ldc + c) = __floats2half2_rn(x2, x3);
            } else {
                if (MODE == 1) {
                    float2 rv0 = *(const float2*)(res + (size_t)r0 * ldc + c);
                    float2 rv1 = *(const float2*)(res + (size_t)(r0+8) * ldc + c);
                    x0 += rv0.x; x1 += rv0.y; x2 += rv1.x; x3 += rv1.y;
                }
                *(float2*)(C + (size_t)r0 * ldc + c)     = make_float2(x0, x1);
                *(float2*)(C + (size_t)(r0+8) * ldc + c) = make_float2(x2, x3);
            }
        }
    }
}

// ---------------------------------------------------------------------------
// Flash attention (fp32, causal, online softmax) -> fp16 z
// ---------------------------------------------------------------------------
__global__ void attn_kernel(const float* __restrict__ Q, const float* __restrict__ K,
                            const float* __restrict__ V, __half* __restrict__ Z) {
    __shared__ float Ks[32][64];
    __shared__ float Vs[32][64];
    int bh = blockIdx.y;
    int b  = bh / N_HEADS;
    int h  = bh % N_HEADS;
    int qi = blockIdx.x * 64 + threadIdx.x;
    int tok = b * SEQ + qi;

    float q[64];
    const float* qp = Q + (size_t)tok * D_MODEL + h * D_HEAD;
#pragma unroll
    for (int d = 0; d < 64; d++) q[d] = qp[d] * 0.125f;   // 1/sqrt(64)

    float m = -INFINITY, l = 0.f;
    float acc[64];
#pragma unroll
    for (int d = 0; d < 64; d++) acc[d] = 0.f;

    int ntiles = (blockIdx.x * 64 + 64 + 31) / 32;
    for (int tt = 0; tt < ntiles; tt++) {
        int kv0 = tt * 32;
        __syncthreads();
        for (int f = threadIdx.x; f < 512; f += 64) {
            int r = f >> 4, c4 = f & 15;
            size_t goff = (size_t)(b*SEQ + kv0 + r) * D_MODEL + h * D_HEAD + c4*4;
            *(float4*)&Ks[r][c4*4] = *(const float4*)(K + goff);
            *(float4*)&Vs[r][c4*4] = *(const float4*)(V + goff);
        }
        __syncthreads();
        int jmax = qi - kv0 + 1;
        if (jmax > 32) jmax = 32;
        for (int j = 0; j < jmax; j++) {
            float s = 0.f;
#pragma unroll
            for (int d4 = 0; d4 < 16; d4++) {
                float4 kk = *(const float4*)&Ks[j][d4*4];
                s = fmaf(q[d4*4+0], kk.x, s);
                s = fmaf(q[d4*4+1], kk.y, s);
                s = fmaf(q[d4*4+2], kk.z, s);
                s = fmaf(q[d4*4+3], kk.w, s);
            }
            float mnew = fmaxf(m, s);
            float fac  = __expf(m - mnew);
            float p    = __expf(s - mnew);
            l = l * fac + p;
#pragma unroll
            for (int d4 = 0; d4 < 16; d4++) {
                float4 vv = *(const float4*)&Vs[j][d4*4];
                acc[d4*4+0] = fmaf(acc[d4*4+0], fac, p * vv.x);
                acc[d4*4+1] = fmaf(acc[d4*4+1], fac, p * vv.y);
                acc[d4*4+2] = fmaf(acc[d4*4+2], fac, p * vv.z);
                acc[d4*4+3] = fmaf(acc[d4*4+3], fac, p * vv.w);
            }
            m = mnew;
        }
    }
    float inv = 1.f / l;
    size_t zoff = (size_t)tok * D_MODEL + h * D_HEAD;
#pragma unroll
    for (int d = 0; d < 64; d += 2) {
        *(__half2*)(Z + zoff + d) = __floats2half2_rn(acc[d] * inv, acc[d+1] * inv);
    }
}

// ---------------------------------------------------------------------------
// launch
// ---------------------------------------------------------------------------
extern "C" void kernel_launch(void* const* d_in, const int* in_sizes, int n_in,
                              void* d_out, int out_size) {
    const float* resid_pre = (const float*)d_in[0];
    const float* ln1_w = (const float*)d_in[1];
    const float* ln1_b = (const float*)d_in[2];
    const float* W_Q   = (const float*)d_in[3];
    const float* b_Q   = (const float*)d_in[4];
    const float* W_K   = (const float*)d_in[5];
    const float* b_K   = (const float*)d_in[6];
    const float* W_V   = (const float*)d_in[7];
    const float* b_V   = (const float*)d_in[8];
    const float* W_O   = (const float*)d_in[9];
    const float* b_O   = (const float*)d_in[10];
    const float* ln2_w = (const float*)d_in[11];
    const float* ln2_b = (const float*)d_in[12];
    const float* W_in  = (const float*)d_in[13];
    const float* b_in  = (const float*)d_in[14];
    const float* W_out = (const float*)d_in[15];
    const float* b_out = (const float*)d_in[16];
    float* out = (float*)d_out;

    __half *p_ln1, *p_z, *p_ln2, *p_mlp, *p_wqkv, *p_wo, *p_win, *p_wout;
    float *p_q, *p_k, *p_v, *p_rmid;

    cudaGetSymbolAddress((void**)&p_ln1,  g_ln1);
    cudaGetSymbolAddress((void**)&p_q,    g_q);
    cudaGetSymbolAddress((void**)&p_k,    g_k);
    cudaGetSymbolAddress((void**)&p_v,    g_v);
    cudaGetSymbolAddress((void**)&p_z,    g_z);
    cudaGetSymbolAddress((void**)&p_rmid, g_rmid);
    cudaGetSymbolAddress((void**)&p_ln2,  g_ln2);
    cudaGetSymbolAddress((void**)&p_mlp,  g_mlp);
    cudaGetSymbolAddress((void**)&p_wqkv, g_wqkv);
    cudaGetSymbolAddress((void**)&p_wo,   g_wo);
    cudaGetSymbolAddress((void**)&p_win,  g_win);
    cudaGetSymbolAddress((void**)&p_wout, g_wout);

    cudaFuncSetAttribute(gemm_h<0,true >, cudaFuncAttributeMaxDynamicSharedMemorySize, GEMM_SMEM);
    cudaFuncSetAttribute(gemm_h<1,false>, cudaFuncAttributeMaxDynamicSharedMemorySize, GEMM_SMEM);
    cudaFuncSetAttribute(gemm_h<2,false>, cudaFuncAttributeMaxDynamicSharedMemorySize, GEMM_SMEM);

    dim3 tb(32, 8);
    // weight prep: transpose to [N,K] fp16; QKV packed into one [3072,1024] buffer
    transpose_h_kernel<<<dim3(2, 32, 16),  tb>>>(W_Q,   p_wqkv,                       D_MODEL, D_HEAD);
    transpose_h_kernel<<<dim3(2, 32, 16),  tb>>>(W_K,   p_wqkv + 1024*D_MODEL,        D_MODEL, D_HEAD);
    transpose_h_kernel<<<dim3(2, 32, 16),  tb>>>(W_V,   p_wqkv + 2048*D_MODEL,        D_MODEL, D_HEAD);
    transpose_h_kernel<<<dim3(32, 32, 1),  tb>>>(W_O,   p_wo,   D_MODEL, D_MODEL);
    transpose_h_kernel<<<dim3(128, 32, 1), tb>>>(W_in,  p_win,  D_MODEL, D_MLP);
    transpose_h_kernel<<<dim3(32, 128, 1), tb>>>(W_out, p_wout, D_MLP,   D_MODEL);

    // 1) LN1 -> fp16
    ln_h_kernel<<<NTOK, 256>>>(resid_pre, ln1_w, ln1_b, p_ln1);

    // 2) fused QKV projection (fp32 out, segment-select)
    dim3 gQKV(3*D_MODEL/128, NTOK/128);
    gemm_h<0,true><<<gQKV, 256, GEMM_SMEM>>>(p_ln1, p_wqkv, b_Q, b_K, b_V, nullptr,
                                             p_q, p_k, p_v, nullptr, NTOK, 3*D_MODEL, D_MODEL);

    // 3) attention -> fp16 z
    attn_kernel<<<dim3(SEQ/64, BATCH*N_HEADS), 64>>>(p_q, p_k, p_v, p_z);

    // 4) O projection + residual -> rmid (fp32)
    dim3 gProj(D_MODEL/128, NTOK/128);
    gemm_h<1,false><<<gProj, 256, GEMM_SMEM>>>(p_z, p_wo, b_O, nullptr, nullptr, resid_pre,
                                               p_rmid, nullptr, nullptr, nullptr, NTOK, D_MODEL, D_MODEL);

    // 5) LN2 -> fp16
    ln_h_kernel<<<NTOK, 256>>>(p_rmid, ln2_w, ln2_b, p_ln2);

    // 6) MLP in + ReLU -> fp16
    dim3 gMlp1(D_MLP/128, NTOK/128);
    gemm_h<2,false><<<gMlp1, 256, GEMM_SMEM>>>(p_ln2, p_win, b_in, nullptr, nullptr, nullptr,
                                               nullptr, nullptr, nullptr, p_mlp, NTOK, D_MLP, D_MODEL);

    // 7) MLP out + residual -> output (fp32)
    gemm_h<1,false><<<gProj, 256, GEMM_SMEM>>>(p_mlp, p_wout, b_out, nullptr, nullptr, p_rmid,
                                               out, nullptr, nullptr, nullptr, NTOK, D_MODEL, D_MLP);
}

// round 8
// speedup vs baseline: 6.3334x; 2.7685x over previous
#include <cuda_runtime.h>
#include <cuda_fp16.h>
#include <math.h>
#include <stdint.h>

#define D_MODEL 1024
#define N_HEADS 16
#define D_HEAD  64
#define D_MLP   4096
#define BATCH   2
#define SEQ     2048
#define NTOK    (BATCH*SEQ)   // 4096
#define LN_EPS  1e-5f

// ---------------------------------------------------------------------------
// scratch (static device globals; no allocation)
// ---------------------------------------------------------------------------
__device__ __half g_ln1[NTOK*D_MODEL];
__device__ __half g_q  [NTOK*D_MODEL];
__device__ __half g_k  [NTOK*D_MODEL];
__device__ __half g_v  [NTOK*D_MODEL];
__device__ __half g_z  [NTOK*D_MODEL];
__device__ float  g_rmid[NTOK*D_MODEL];
__device__ __half g_ln2[NTOK*D_MODEL];
__device__ __half g_mlp[(size_t)NTOK*D_MLP];
// transposed fp16 weights ([N,K] row-major, k-contiguous)
__device__ __half g_wqkv[3*D_MODEL*D_MODEL];     // rows 0..1023 Q, 1024..2047 K, 2048..3071 V
__device__ __half g_wo  [D_MODEL*D_MODEL];
__device__ __half g_win [(size_t)D_MLP*D_MODEL];
__device__ __half g_wout[(size_t)D_MODEL*D_MLP];

// ---------------------------------------------------------------------------
// helpers
// ---------------------------------------------------------------------------
__device__ __forceinline__ uint32_t smem_to_u32(const void* p) {
    uint32_t a;
    asm("{ .reg .u64 t; cvta.to.shared.u64 t, %1; cvt.u32.u64 %0, t; }" : "=r"(a) : "l"(p));
    return a;
}
__device__ __forceinline__ void cp16(uint32_t s, const void* g) {
    asm volatile("cp.async.cg.shared.global [%0], [%1], 16;" :: "r"(s), "l"(g));
}
__device__ __forceinline__ void ldmx4(uint32_t* r, uint32_t addr) {
    asm volatile("ldmatrix.sync.aligned.m8n8.x4.shared.b16 {%0,%1,%2,%3}, [%4];"
        : "=r"(r[0]), "=r"(r[1]), "=r"(r[2]), "=r"(r[3]) : "r"(addr));
}
__device__ __forceinline__ void ldmx4t(uint32_t* r, uint32_t addr) {
    asm volatile("ldmatrix.sync.aligned.m8n8.x4.trans.shared.b16 {%0,%1,%2,%3}, [%4];"
        : "=r"(r[0]), "=r"(r[1]), "=r"(r[2]), "=r"(r[3]) : "r"(addr));
}
__device__ __forceinline__ void mma16816(float* d, const uint32_t* a, uint32_t b0, uint32_t b1) {
    asm volatile("mma.sync.aligned.m16n8k16.row.col.f32.f16.f16.f32 "
        "{%0,%1,%2,%3}, {%4,%5,%6,%7}, {%8,%9}, {%0,%1,%2,%3};"
        : "+f"(d[0]), "+f"(d[1]), "+f"(d[2]), "+f"(d[3])
        : "r"(a[0]), "r"(a[1]), "r"(a[2]), "r"(a[3]), "r"(b0), "r"(b1));
}
__device__ __forceinline__ uint32_t packh2(float x, float y) {
    __half2 h = __floats2half2_rn(x, y);
    return *(uint32_t*)&h;
}

// ---------------------------------------------------------------------------
// weight transpose: src is batch x [K,N] fp32 row-major -> fp16 [batch*N, K]
// ---------------------------------------------------------------------------
__global__ void transpose_h_kernel(const float* __restrict__ src,
                                   __half* __restrict__ dst,
                                   int K, int N) {
    __shared__ float t[32][33];
    int b  = blockIdx.z;
    int n0 = blockIdx.x * 32, k0 = blockIdx.y * 32;
    const float* s = src + (size_t)b * K * N;
#pragma unroll
    for (int i = 0; i < 4; i++)
        t[threadIdx.y + i*8][threadIdx.x] = s[(size_t)(k0 + threadIdx.y + i*8) * N + n0 + threadIdx.x];
    __syncthreads();
#pragma unroll
    for (int i = 0; i < 4; i++) {
        float v = t[threadIdx.x][threadIdx.y + i*8];
        size_t o = (size_t)(b * N + n0 + threadIdx.y + i*8) * K + k0 + threadIdx.x;
        dst[o] = __float2half_rn(v);
    }
}

// ---------------------------------------------------------------------------
// LayerNorm -> fp16
// ---------------------------------------------------------------------------
__global__ void ln_h_kernel(const float* __restrict__ x, const float* __restrict__ w,
                            const float* __restrict__ b, __half* __restrict__ o) {
    int row = blockIdx.x;
    const float* xr = x + (size_t)row * D_MODEL;
    float vals[4];
    float s = 0.f, s2 = 0.f;
#pragma unroll
    for (int i = 0; i < 4; i++) {
        float v = xr[threadIdx.x + i*256];
        vals[i] = v; s += v; s2 += v*v;
    }
#pragma unroll
    for (int off = 16; off > 0; off >>= 1) {
        s  += __shfl_xor_sync(0xFFFFFFFFu, s,  off);
        s2 += __shfl_xor_sync(0xFFFFFFFFu, s2, off);
    }
    __shared__ float sh[2][8];
    int wid = threadIdx.x >> 5, lid = threadIdx.x & 31;
    if (lid == 0) { sh[0][wid] = s; sh[1][wid] = s2; }
    __syncthreads();
    s = 0.f; s2 = 0.f;
#pragma unroll
    for (int i = 0; i < 8; i++) { s += sh[0][i]; s2 += sh[1][i]; }
    float mean = s * (1.f/(float)D_MODEL);
    float var  = s2 * (1.f/(float)D_MODEL) - mean*mean;
    float rstd = rsqrtf(var + LN_EPS);
#pragma unroll
    for (int i = 0; i < 4; i++) {
        int c = threadIdx.x + i*256;
        float v = (vals[i] - mean) * rstd * w[c] + b[c];
        o[(size_t)row * D_MODEL + c] = __float2half_rn(v);
    }
}

// ---------------------------------------------------------------------------
// fp16 HMMA GEMM: C[M,N] = A[M,K] @ B^T  (B stored [N,K] fp16)
// CTA tile 128x128, BK=32, 256 threads, cp.async double buffer, 2 CTAs/SM.
// MODE 1: fp32 C0 = acc + bias + res
// MODE 2: fp16 Ch0 = relu(acc + bias)
// MODE 3: fp16 Ch{0,1,2} = acc + bias   (SEG: segment-select by bn>>10, ldc=1024)
// ---------------------------------------------------------------------------
#define TILE_B    10240              // 128 rows * 80 bytes
#define STAGE_B   (2*TILE_B)         // A + B tiles
#define GEMM_SMEM (2*STAGE_B)        // 40960 (double buffered)

template<int MODE, bool SEG>
__global__ void __launch_bounds__(256, 2) gemm_h(
    const __half* __restrict__ A, const __half* __restrict__ B,
    const float* __restrict__ b0, const float* __restrict__ b1, const float* __restrict__ b2,
    const float* __restrict__ res,
    float* __restrict__ C0,
    __half* __restrict__ Ch0, __half* __restrict__ Ch1, __half* __restrict__ Ch2,
    int M, int N, int K)
{
    extern __shared__ __align__(128) char smem[];
    const uint32_t sbase = smem_to_u32(smem);
    const int tid  = threadIdx.x;
    const int lane = tid & 31;
    const int wid  = tid >> 5;
    const int wm   = wid >> 2;
    const int wn   = wid & 3;
    const int bm   = blockIdx.y * 128;
    const int bn   = blockIdx.x * 128;

    const float* bias = b0;
    __half* Chx = Ch0;
    int bnl = bn, ldc = N;
    if (SEG) {
        int sg = bn >> 10;
        bias = (sg == 0) ? b0 : (sg == 1) ? b1 : b2;
        Chx  = (sg == 0) ? Ch0 : (sg == 1) ? Ch1 : Ch2;
        bnl  = bn & 1023;
        ldc  = 1024;
    }

    float acc[4][4][4];
#pragma unroll
    for (int i = 0; i < 4; i++)
#pragma unroll
        for (int j = 0; j < 4; j++)
#pragma unroll
            for (int q = 0; q < 4; q++) acc[i][j][q] = 0.f;

    const int nk = K >> 5;

    auto load_stage = [&](int kt, int buf) {
        const int k0 = kt << 5;
        const uint32_t sb0 = sbase + buf * STAGE_B;
#pragma unroll
        for (int u = 0; u < 2; u++) {
            int f   = tid + u * 256;
            int row = f >> 2, c = f & 3;
            uint32_t soff = (uint32_t)(row * 80 + c * 16);
            cp16(sb0 + 0*TILE_B + soff, A + (size_t)(bm + row) * K + k0 + c * 8);
            cp16(sb0 + 1*TILE_B + soff, B + (size_t)(bn + row) * K + k0 + c * 8);
        }
    };

    const uint32_t aRowOff = (uint32_t)((wm*64 + (lane & 15)) * 80 + (lane >> 4) * 16);
    const uint32_t bRowOff = (uint32_t)((wn*32 + (lane & 15)) * 80 + (lane >> 4) * 16);

    load_stage(0, 0);
    asm volatile("cp.async.commit_group;");

    for (int kt = 0; kt < nk; kt++) {
        if (kt + 1 < nk) {
            load_stage(kt + 1, (kt + 1) & 1);
            asm volatile("cp.async.commit_group;");
            asm volatile("cp.async.wait_group 1;");
        } else {
            asm volatile("cp.async.wait_group 0;");
        }
        __syncthreads();

        const uint32_t sb0 = sbase + (kt & 1) * STAGE_B;
#pragma unroll
        for (int ks = 0; ks < 2; ks++) {
            const uint32_t koff = ks * 32;
            uint32_t a[4][4], bb[2][4];
#pragma unroll
            for (int i = 0; i < 4; i++)
                ldmx4(a[i], sb0 + 0*TILE_B + aRowOff + (uint32_t)(i*16*80) + koff);
#pragma unroll
            for (int j = 0; j < 2; j++)
                ldmx4(bb[j], sb0 + 1*TILE_B + bRowOff + (uint32_t)(j*16*80) + koff);
#pragma unroll
            for (int i = 0; i < 4; i++)
#pragma unroll
                for (int nb = 0; nb < 4; nb++) {
                    int j = nb >> 1, sel = nb & 1;
                    mma16816(acc[i][nb], a[i], bb[j][sel], bb[j][sel + 2]);
                }
        }
        __syncthreads();
    }

    // --- epilogue ---
    const int mrow = bm + wm*64 + (lane >> 2);
    const int ncol = bnl + wn*32 + (lane & 3) * 2;
#pragma unroll
    for (int i = 0; i < 4; i++) {
#pragma unroll
        for (int jj = 0; jj < 4; jj++) {
            int r0 = mrow + i*16;
            int c  = ncol + jj*8;
            float2 bv = *(const float2*)(bias + c);
            float x0 = acc[i][jj][0] + bv.x;
            float x1 = acc[i][jj][1] + bv.y;
            float x2 = acc[i][jj][2] + bv.x;
            float x3 = acc[i][jj][3] + bv.y;
            if (MODE == 2) {
                x0 = fmaxf(x0, 0.f); x1 = fmaxf(x1, 0.f);
                x2 = fmaxf(x2, 0.f); x3 = fmaxf(x3, 0.f);
                *(__half2*)(Chx + (size_t)r0 * ldc + c)     = __floats2half2_rn(x0, x1);
                *(__half2*)(Chx + (size_t)(r0+8) * ldc + c) = __floats2half2_rn(x2, x3);
            } else if (MODE == 3) {
                *(__half2*)(Chx + (size_t)r0 * ldc + c)     = __floats2half2_rn(x0, x1);
                *(__half2*)(Chx + (size_t)(r0+8) * ldc + c) = __floats2half2_rn(x2, x3);
            } else {
                float2 rv0 = *(const float2*)(res + (size_t)r0 * ldc + c);
                float2 rv1 = *(const float2*)(res + (size_t)(r0+8) * ldc + c);
                x0 += rv0.x; x1 += rv0.y; x2 += rv1.x; x3 += rv1.y;
                *(float2*)(C0 + (size_t)r0 * ldc + c)     = make_float2(x0, x1);
                *(float2*)(C0 + (size_t)(r0+8) * ldc + c) = make_float2(x2, x3);
            }
        }
    }
}

// ---------------------------------------------------------------------------
// HMMA flash attention (fp16 in, fp32 accum, causal) -> fp16 z
// CTA: 64 q-rows x one (b,h); 4 warps, 16 q-rows/warp.
// KV tiles of 64, cp.async double buffer, smem rows 144B (conflict-free ldmatrix)
// ---------------------------------------------------------------------------
__global__ void __launch_bounds__(128) attn_hmma(
    const __half* __restrict__ Q, const __half* __restrict__ K,
    const __half* __restrict__ V, __half* __restrict__ Z)
{
    __shared__ __align__(16) __half sQ[64*72];
    __shared__ __align__(16) __half sK[2][64*72];
    __shared__ __align__(16) __half sV[2][64*72];
    const int tid = threadIdx.x, lane = tid & 31, wid = tid >> 5;
    const int qblk = (SEQ/64 - 1) - blockIdx.x;     // heavy blocks first
    const int bh = blockIdx.y, b = bh >> 4, h = bh & 15;
    const uint32_t uQ = smem_to_u32(sQ);
    const uint32_t uK = smem_to_u32(sK);
    const uint32_t uV = smem_to_u32(sV);
    const size_t qbase = ((size_t)(b*SEQ + qblk*64)) * D_MODEL + h * D_HEAD;

    // Q + stage0 loads (one commit group)
    for (int f = tid; f < 512; f += 128) {
        int row = f >> 3, c = f & 7;
        cp16(uQ + row*144 + c*16, Q + qbase + (size_t)row * D_MODEL + c*8);
    }
    auto load_kv = [&](int kt, int buf) {
        size_t base = ((size_t)(b*SEQ + kt*64)) * D_MODEL + h * D_HEAD;
        for (int f = tid; f < 512; f += 128) {
            int row = f >> 3, c = f & 7;
            cp16(uK + buf*(64*144) + row*144 + c*16, K + base + (size_t)row * D_MODEL + c*8);
            cp16(uV + buf*(64*144) + row*144 + c*16, V + base + (size_t)row * D_MODEL + c*8);
        }
    };
    load_kv(0, 0);
    asm volatile("cp.async.commit_group;");

    float oacc[8][4];
#pragma unroll
    for (int i = 0; i < 8; i++)
#pragma unroll
        for (int c = 0; c < 4; c++) oacc[i][c] = 0.f;
    float m0 = -INFINITY, m1 = -INFINITY, l0 = 0.f, l1 = 0.f;
    uint32_t a[4][4];

    const int ntiles = qblk + 1;
    for (int kt = 0; kt < ntiles; kt++) {
        if (kt + 1 < ntiles) {
            load_kv(kt + 1, (kt + 1) & 1);
            asm volatile("cp.async.commit_group;");
            asm volatile("cp.async.wait_group 1;");
        } else {
            asm volatile("cp.async.wait_group 0;");
        }
        __syncthreads();

        if (kt == 0) {
#pragma unroll
            for (int kk = 0; kk < 4; kk++)
                ldmx4(a[kk], uQ + (uint32_t)((wid*16 + (lane & 15))*144 + kk*32 + (lane >> 4)*16));
        }

        // S = Q K^T
        const uint32_t kb0 = uK + (uint32_t)((kt & 1) * (64*144));
        float sc[8][4];
#pragma unroll
        for (int i = 0; i < 8; i++)
#pragma unroll
            for (int c = 0; c < 4; c++) sc[i][c] = 0.f;
#pragma unroll
        for (int kk = 0; kk < 4; kk++) {
            uint32_t kb[4][4];
#pragma unroll
            for (int j = 0; j < 4; j++)
                ldmx4(kb[j], kb0 + (uint32_t)((j*16 + (lane & 15))*144 + kk*32 + (lane >> 4)*16));
#pragma unroll
            for (int j = 0; j < 4; j++) {
                mma16816(sc[2*j],   a[kk], kb[j][0], kb[j][2]);
                mma16816(sc[2*j+1], a[kk], kb[j][1], kb[j][3]);
            }
        }

        // softmax (online)
        const float scale = 0.125f;   // 1/sqrt(64)
        const bool diag = (kt == qblk);
        const int q0 = wid*16 + (lane >> 2);
        float mx0 = m0, mx1 = m1;
#pragma unroll
        for (int nb = 0; nb < 8; nb++) {
#pragma unroll
            for (int c = 0; c < 4; c++) {
                float s = sc[nb][c] * scale;
                if (diag) {
                    int jg = nb*8 + (lane & 3)*2 + (c & 1);
                    int qg = q0 + ((c >> 1) << 3);
                    if (jg > qg) s = -INFINITY;
                }
                sc[nb][c] = s;
            }
            mx0 = fmaxf(mx0, fmaxf(sc[nb][0], sc[nb][1]));
            mx1 = fmaxf(mx1, fmaxf(sc[nb][2], sc[nb][3]));
        }
        mx0 = fmaxf(mx0, __shfl_xor_sync(0xFFFFFFFFu, mx0, 1));
        mx0 = fmaxf(mx0, __shfl_xor_sync(0xFFFFFFFFu, mx0, 2));
        mx1 = fmaxf(mx1, __shfl_xor_sync(0xFFFFFFFFu, mx1, 1));
        mx1 = fmaxf(mx1, __shfl_xor_sync(0xFFFFFFFFu, mx1, 2));
        float fac0 = __expf(m0 - mx0), fac1 = __expf(m1 - mx1);
        m0 = mx0; m1 = mx1;
        float ls0 = 0.f, ls1 = 0.f;
#pragma unroll
        for (int nb = 0; nb < 8; nb++) {
            sc[nb][0] = __expf(sc[nb][0] - mx0);
            sc[nb][1] = __expf(sc[nb][1] - mx0);
            sc[nb][2] = __expf(sc[nb][2] - mx1);
            sc[nb][3] = __expf(sc[nb][3] - mx1);
            ls0 += sc[nb][0] + sc[nb][1];
            ls1 += sc[nb][2] + sc[nb][3];
        }
        l0 = l0 * fac0 + ls0;
        l1 = l1 * fac1 + ls1;
#pragma unroll
        for (int nb = 0; nb < 8; nb++) {
            oacc[nb][0] *= fac0; oacc[nb][1] *= fac0;
            oacc[nb][2] *= fac1; oacc[nb][3] *= fac1;
        }

        // O += P V
        const uint32_t vb0 = uV + (uint32_t)((kt & 1) * (64*144));
#pragma unroll
        for (int kk = 0; kk < 4; kk++) {
            uint32_t pa[4];
            pa[0] = packh2(sc[2*kk][0],   sc[2*kk][1]);
            pa[1] = packh2(sc[2*kk][2],   sc[2*kk][3]);
            pa[2] = packh2(sc[2*kk+1][0], sc[2*kk+1][1]);
            pa[3] = packh2(sc[2*kk+1][2], sc[2*kk+1][3]);
#pragma unroll
            for (int j = 0; j < 4; j++) {
                uint32_t vb[4];
                ldmx4t(vb, vb0 + (uint32_t)((kk*16 + (lane & 15))*144 + j*32 + (lane >> 4)*16));
                mma16816(oacc[2*j],   pa, vb[0], vb[1]);
                mma16816(oacc[2*j+1], pa, vb[2], vb[3]);
            }
        }
        __syncthreads();
    }

    // normalize + store
    l0 += __shfl_xor_sync(0xFFFFFFFFu, l0, 1);
    l0 += __shfl_xor_sync(0xFFFFFFFFu, l0, 2);
    l1 += __shfl_xor_sync(0xFFFFFFFFu, l1, 1);
    l1 += __shfl_xor_sync(0xFFFFFFFFu, l1, 2);
    float i0 = 1.f / l0, i1 = 1.f / l1;
    size_t tok0 = (size_t)(b*SEQ + qblk*64 + wid*16 + (lane >> 2));
    size_t zb0 = tok0 * D_MODEL + h * D_HEAD + (lane & 3)*2;
    size_t zb1 = zb0 + (size_t)8 * D_MODEL;
#pragma unroll
    for (int nb = 0; nb < 8; nb++) {
        *(__half2*)(Z + zb0 + nb*8) = __floats2half2_rn(oacc[nb][0]*i0, oacc[nb][1]*i0);
        *(__half2*)(Z + zb1 + nb*8) = __floats2half2_rn(oacc[nb][2]*i1, oacc[nb][3]*i1);
    }
}

// ---------------------------------------------------------------------------
// launch
// ---------------------------------------------------------------------------
extern "C" void kernel_launch(void* const* d_in, const int* in_sizes, int n_in,
                              void* d_out, int out_size) {
    const float* resid_pre = (const float*)d_in[0];
    const float* ln1_w = (const float*)d_in[1];
    const float* ln1_b = (const float*)d_in[2];
    const float* W_Q   = (const float*)d_in[3];
    const float* b_Q   = (const float*)d_in[4];
    const float* W_K   = (const float*)d_in[5];
    const float* b_K   = (const float*)d_in[6];
    const float* W_V   = (const float*)d_in[7];
    const float* b_V   = (const float*)d_in[8];
    const float* W_O   = (const float*)d_in[9];
    const float* b_O   = (const float*)d_in[10];
    const float* ln2_w = (const float*)d_in[11];
    const float* ln2_b = (const float*)d_in[12];
    const float* W_in  = (const float*)d_in[13];
    const float* b_in  = (const float*)d_in[14];
    const float* W_out = (const float*)d_in[15];
    const float* b_out = (const float*)d_in[16];
    float* out = (float*)d_out;

    __half *p_ln1, *p_q, *p_k, *p_v, *p_z, *p_ln2, *p_mlp, *p_wqkv, *p_wo, *p_win, *p_wout;
    float *p_rmid;

    cudaGetSymbolAddress((void**)&p_ln1,  g_ln1);
    cudaGetSymbolAddress((void**)&p_q,    g_q);
    cudaGetSymbolAddress((void**)&p_k,    g_k);
    cudaGetSymbolAddress((void**)&p_v,    g_v);
    cudaGetSymbolAddress((void**)&p_z,    g_z);
    cudaGetSymbolAddress((void**)&p_rmid, g_rmid);
    cudaGetSymbolAddress((void**)&p_ln2,  g_ln2);
    cudaGetSymbolAddress((void**)&p_mlp,  g_mlp);
    cudaGetSymbolAddress((void**)&p_wqkv, g_wqkv);
    cudaGetSymbolAddress((void**)&p_wo,   g_wo);
    cudaGetSymbolAddress((void**)&p_win,  g_win);
    cudaGetSymbolAddress((void**)&p_wout, g_wout);

    cudaFuncSetAttribute(gemm_h<1,false>, cudaFuncAttributeMaxDynamicSharedMemorySize, GEMM_SMEM);
    cudaFuncSetAttribute(gemm_h<2,false>, cudaFuncAttributeMaxDynamicSharedMemorySize, GEMM_SMEM);
    cudaFuncSetAttribute(gemm_h<3,true >, cudaFuncAttributeMaxDynamicSharedMemorySize, GEMM_SMEM);

    dim3 tb(32, 8);
    // weight prep: transpose to [N,K] fp16; QKV packed into one [3072,1024] buffer
    transpose_h_kernel<<<dim3(2, 32, 16),  tb>>>(W_Q,   p_wqkv,                D_MODEL, D_HEAD);
    transpose_h_kernel<<<dim3(2, 32, 16),  tb>>>(W_K,   p_wqkv + 1024*D_MODEL, D_MODEL, D_HEAD);
    transpose_h_kernel<<<dim3(2, 32, 16),  tb>>>(W_V,   p_wqkv + 2048*D_MODEL, D_MODEL, D_HEAD);
    transpose_h_kernel<<<dim3(32, 32, 1),  tb>>>(W_O,   p_wo,   D_MODEL, D_MODEL);
    transpose_h_kernel<<<dim3(128, 32, 1), tb>>>(W_in,  p_win,  D_MODEL, D_MLP);
    transpose_h_kernel<<<dim3(32, 128, 1), tb>>>(W_out, p_wout, D_MLP,   D_MODEL);

    // 1) LN1 -> fp16
    ln_h_kernel<<<NTOK, 256>>>(resid_pre, ln1_w, ln1_b, p_ln1);

    // 2) fused QKV projection -> fp16 q,k,v (segment-select)
    dim3 gQKV(3*D_MODEL/128, NTOK/128);
    gemm_h<3,true><<<gQKV, 256, GEMM_SMEM>>>(p_ln1, p_wqkv, b_Q, b_K, b_V, nullptr,
                                             nullptr, p_q, p_k, p_v, NTOK, 3*D_MODEL, D_MODEL);

    // 3) HMMA flash attention -> fp16 z
    attn_hmma<<<dim3(SEQ/64, BATCH*N_HEADS), 128>>>(p_q, p_k, p_v, p_z);

    // 4) O projection + residual -> rmid (fp32)
    dim3 gProj(D_MODEL/128, NTOK/128);
    gemm_h<1,false><<<gProj, 256, GEMM_SMEM>>>(p_z, p_wo, b_O, nullptr, nullptr, resid_pre,
                                               p_rmid, nullptr, nullptr, nullptr, NTOK, D_MODEL, D_MODEL);

    // 5) LN2 -> fp16
    ln_h_kernel<<<NTOK, 256>>>(p_rmid, ln2_w, ln2_b, p_ln2);

    // 6) MLP in + ReLU -> fp16
    dim3 gMlp1(D_MLP/128, NTOK/128);
    gemm_h<2,false><<<gMlp1, 256, GEMM_SMEM>>>(p_ln2, p_win, b_in, nullptr, nullptr, nullptr,
                                               nullptr, p_mlp, nullptr, nullptr, NTOK, D_MLP, D_MODEL);

    // 7) MLP out + residual -> output (fp32)
    gemm_h<1,false><<<gProj, 256, GEMM_SMEM>>>(p_mlp, p_wout, b_out, nullptr, nullptr, p_rmid,
                                               out, nullptr, nullptr, nullptr, NTOK, D_MODEL, D_MLP);
}

// round 9
// speedup vs baseline: 6.7179x; 1.0607x over previous
#include <cuda_runtime.h>
#include <cuda_fp16.h>
#include <math.h>
#include <stdint.h>

#define D_MODEL 1024
#define N_HEADS 16
#define D_HEAD  64
#define D_MLP   4096
#define BATCH   2
#define SEQ     2048
#define NTOK    (BATCH*SEQ)   // 4096
#define LN_EPS  1e-5f

// ---------------------------------------------------------------------------
// scratch (static device globals; no allocation)
// ---------------------------------------------------------------------------
__device__ __half g_ln1[NTOK*D_MODEL];
__device__ __half g_q  [NTOK*D_MODEL];
__device__ __half g_k  [NTOK*D_MODEL];
__device__ __half g_v  [NTOK*D_MODEL];
__device__ __half g_z  [NTOK*D_MODEL];
__device__ float  g_rmid[NTOK*D_MODEL];
__device__ __half g_ln2[NTOK*D_MODEL];
__device__ __half g_mlp[(size_t)NTOK*D_MLP];
// transposed fp16 weights ([N,K] row-major, k-contiguous)
__device__ __half g_wqkv[3*D_MODEL*D_MODEL];     // rows 0..1023 Q, 1024..2047 K, 2048..3071 V
__device__ __half g_wo  [D_MODEL*D_MODEL];
__device__ __half g_win [(size_t)D_MLP*D_MODEL];
__device__ __half g_wout[(size_t)D_MODEL*D_MLP];

// ---------------------------------------------------------------------------
// helpers
// ---------------------------------------------------------------------------
__device__ __forceinline__ uint32_t smem_to_u32(const void* p) {
    uint32_t a;
    asm("{ .reg .u64 t; cvta.to.shared.u64 t, %1; cvt.u32.u64 %0, t; }" : "=r"(a) : "l"(p));
    return a;
}
__device__ __forceinline__ void cp16(uint32_t s, const void* g) {
    asm volatile("cp.async.cg.shared.global [%0], [%1], 16;" :: "r"(s), "l"(g));
}
__device__ __forceinline__ void ldmx4(uint32_t* r, uint32_t addr) {
    asm volatile("ldmatrix.sync.aligned.m8n8.x4.shared.b16 {%0,%1,%2,%3}, [%4];"
        : "=r"(r[0]), "=r"(r[1]), "=r"(r[2]), "=r"(r[3]) : "r"(addr));
}
__device__ __forceinline__ void ldmx4t(uint32_t* r, uint32_t addr) {
    asm volatile("ldmatrix.sync.aligned.m8n8.x4.trans.shared.b16 {%0,%1,%2,%3}, [%4];"
        : "=r"(r[0]), "=r"(r[1]), "=r"(r[2]), "=r"(r[3]) : "r"(addr));
}
__device__ __forceinline__ void mma16816(float* d, const uint32_t* a, uint32_t b0, uint32_t b1) {
    asm volatile("mma.sync.aligned.m16n8k16.row.col.f32.f16.f16.f32 "
        "{%0,%1,%2,%3}, {%4,%5,%6,%7}, {%8,%9}, {%0,%1,%2,%3};"
        : "+f"(d[0]), "+f"(d[1]), "+f"(d[2]), "+f"(d[3])
        : "r"(a[0]), "r"(a[1]), "r"(a[2]), "r"(a[3]), "r"(b0), "r"(b1));
}
__device__ __forceinline__ uint32_t packh2(float x, float y) {
    __half2 h = __floats2half2_rn(x, y);
    return *(uint32_t*)&h;
}

// ---------------------------------------------------------------------------
// weight transpose: src is batch x [K,N] fp32 row-major -> fp16 [batch*N, K]
// 64x64 tiles, float4 loads, uint4 fp16 stores.
// ---------------------------------------------------------------------------
__global__ void transpose_h2(const float* __restrict__ src,
                             __half* __restrict__ dst,
                             int K, int N) {
    __shared__ float t[64][65];
    const int n0 = blockIdx.x * 64, k0 = blockIdx.y * 64, b = blockIdx.z;
    const float* s = src + (size_t)b * K * N;
    const int tid = threadIdx.x;
    // load: 64 k-rows x 16 float4 along n; 256 threads, 4 rows each
    {
        int c4 = tid & 15, r = tid >> 4;
#pragma unroll
        for (int i = 0; i < 4; i++) {
            float4 v = *(const float4*)(s + (size_t)(k0 + r + i*16) * N + n0 + c4*4);
            t[r + i*16][c4*4+0] = v.x;
            t[r + i*16][c4*4+1] = v.y;
            t[r + i*16][c4*4+2] = v.z;
            t[r + i*16][c4*4+3] = v.w;
        }
    }
    __syncthreads();
    // store: each thread writes 8 halves (16B) along k for one n
    {
        int kg = (tid & 7) * 8;
#pragma unroll
        for (int p = 0; p < 2; p++) {
            int n = (tid >> 3) + p*32;
            __half h[8];
#pragma unroll
            for (int q = 0; q < 8; q++) h[q] = __float2half_rn(t[kg + q][n]);
            *(uint4*)(dst + (size_t)(b * N + n0 + n) * K + k0 + kg) = *(uint4*)h;
        }
    }
}

// ---------------------------------------------------------------------------
// LayerNorm -> fp16
// ---------------------------------------------------------------------------
__global__ void ln_h_kernel(const float* __restrict__ x, const float* __restrict__ w,
                            const float* __restrict__ b, __half* __restrict__ o) {
    int row = blockIdx.x;
    const float* xr = x + (size_t)row * D_MODEL;
    float vals[4];
    float s = 0.f, s2 = 0.f;
#pragma unroll
    for (int i = 0; i < 4; i++) {
        float v = xr[threadIdx.x + i*256];
        vals[i] = v; s += v; s2 += v*v;
    }
#pragma unroll
    for (int off = 16; off > 0; off >>= 1) {
        s  += __shfl_xor_sync(0xFFFFFFFFu, s,  off);
        s2 += __shfl_xor_sync(0xFFFFFFFFu, s2, off);
    }
    __shared__ float sh[2][8];
    int wid = threadIdx.x >> 5, lid = threadIdx.x & 31;
    if (lid == 0) { sh[0][wid] = s; sh[1][wid] = s2; }
    __syncthreads();
    s = 0.f; s2 = 0.f;
#pragma unroll
    for (int i = 0; i < 8; i++) { s += sh[0][i]; s2 += sh[1][i]; }
    float mean = s * (1.f/(float)D_MODEL);
    float var  = s2 * (1.f/(float)D_MODEL) - mean*mean;
    float rstd = rsqrtf(var + LN_EPS);
#pragma unroll
    for (int i = 0; i < 4; i++) {
        int c = threadIdx.x + i*256;
        float v = (vals[i] - mean) * rstd * w[c] + b[c];
        o[(size_t)row * D_MODEL + c] = __float2half_rn(v);
    }
}

// ---------------------------------------------------------------------------
// fp16 HMMA GEMM: C[M,N] = A[M,K] @ B^T  (B stored [N,K] fp16)
// CTA tile 128x128, BK=32, 256 threads, 3-stage cp.async pipeline,
// ONE __syncthreads per k-iteration, 2 CTAs/SM.
// MODE 1: fp32 C0 = acc + bias + res
// MODE 2: fp16 Ch0 = relu(acc + bias)
// MODE 3: fp16 Ch{0,1,2} = acc + bias   (SEG: segment-select by bn>>10, ldc=1024)
// ---------------------------------------------------------------------------
#define TILE_B    10240              // 128 rows * 80 bytes
#define STAGE_B   (2*TILE_B)         // A + B tiles
#define NSTAGE    3
#define GEMM_SMEM (NSTAGE*STAGE_B)   // 61440

template<int MODE, bool SEG>
__global__ void __launch_bounds__(256, 2) gemm_h(
    const __half* __restrict__ A, const __half* __restrict__ B,
    const float* __restrict__ b0, const float* __restrict__ b1, const float* __restrict__ b2,
    const float* __restrict__ res,
    float* __restrict__ C0,
    __half* __restrict__ Ch0, __half* __restrict__ Ch1, __half* __restrict__ Ch2,
    int M, int N, int K)
{
    extern __shared__ __align__(128) char smem[];
    const uint32_t sbase = smem_to_u32(smem);
    const int tid  = threadIdx.x;
    const int lane = tid & 31;
    const int wid  = tid >> 5;
    const int wm   = wid >> 2;
    const int wn   = wid & 3;
    const int bm   = blockIdx.y * 128;
    const int bn   = blockIdx.x * 128;

    const float* bias = b0;
    __half* Chx = Ch0;
    int bnl = bn, ldc = N;
    if (SEG) {
        int sg = bn >> 10;
        bias = (sg == 0) ? b0 : (sg == 1) ? b1 : b2;
        Chx  = (sg == 0) ? Ch0 : (sg == 1) ? Ch1 : Ch2;
        bnl  = bn & 1023;
        ldc  = 1024;
    }

    float acc[4][4][4];
#pragma unroll
    for (int i = 0; i < 4; i++)
#pragma unroll
        for (int j = 0; j < 4; j++)
#pragma unroll
            for (int q = 0; q < 4; q++) acc[i][j][q] = 0.f;

    const int nk = K >> 5;

    auto load_stage = [&](int kt, int buf) {
        const int k0 = kt << 5;
        const uint32_t sb0 = sbase + buf * STAGE_B;
#pragma unroll
        for (int u = 0; u < 2; u++) {
            int f   = tid + u * 256;
            int row = f >> 2, c = f & 3;
            uint32_t soff = (uint32_t)(row * 80 + c * 16);
            cp16(sb0 + 0*TILE_B + soff, A + (size_t)(bm + row) * K + k0 + c * 8);
            cp16(sb0 + 1*TILE_B + soff, B + (size_t)(bn + row) * K + k0 + c * 8);
        }
    };

    const uint32_t aRowOff = (uint32_t)((wm*64 + (lane & 15)) * 80 + (lane >> 4) * 16);
    const uint32_t bRowOff = (uint32_t)((wn*32 + (lane & 15)) * 80 + (lane >> 4) * 16);

    // prologue: stages 0, 1
    load_stage(0, 0);
    asm volatile("cp.async.commit_group;");
    load_stage(1, 1);
    asm volatile("cp.async.commit_group;");

    for (int kt = 0; kt < nk; kt++) {
        // stage kt must be resident: keep at most 1 newer group pending
        if (kt < nk - 1) asm volatile("cp.async.wait_group 1;" ::: "memory");
        else             asm volatile("cp.async.wait_group 0;" ::: "memory");
        __syncthreads();   // single barrier: also proves all warps done compute(kt-1)

        const uint32_t sb0 = sbase + (uint32_t)(kt % NSTAGE) * STAGE_B;
#pragma unroll
        for (int ks = 0; ks < 2; ks++) {
            const uint32_t koff = ks * 32;
            uint32_t a[4][4], bb[2][4];
#pragma unroll
            for (int i = 0; i < 4; i++)
                ldmx4(a[i], sb0 + 0*TILE_B + aRowOff + (uint32_t)(i*16*80) + koff);
#pragma unroll
            for (int j = 0; j < 2; j++)
                ldmx4(bb[j], sb0 + 1*TILE_B + bRowOff + (uint32_t)(j*16*80) + koff);
#pragma unroll
            for (int i = 0; i < 4; i++)
#pragma unroll
                for (int nb = 0; nb < 4; nb++) {
                    int j = nb >> 1, sel = nb & 1;
                    mma16816(acc[i][nb], a[i], bb[j][sel], bb[j][sel + 2]);
                }
        }

        // prefetch stage kt+2 into slot (kt+2)%3 (last read in compute(kt-1))
        if (kt + 2 < nk) {
            load_stage(kt + 2, (kt + 2) % NSTAGE);
            asm volatile("cp.async.commit_group;");
        }
    }

    // --- epilogue ---
    const int mrow = bm + wm*64 + (lane >> 2);
    const int ncol = bnl + wn*32 + (lane & 3) * 2;
#pragma unroll
    for (int i = 0; i < 4; i++) {
#pragma unroll
        for (int jj = 0; jj < 4; jj++) {
            int r0 = mrow + i*16;
            int c  = ncol + jj*8;
            float2 bv = *(const float2*)(bias + c);
            float x0 = acc[i][jj][0] + bv.x;
            float x1 = acc[i][jj][1] + bv.y;
            float x2 = acc[i][jj][2] + bv.x;
            float x3 = acc[i][jj][3] + bv.y;
            if (MODE == 2) {
                x0 = fmaxf(x0, 0.f); x1 = fmaxf(x1, 0.f);
                x2 = fmaxf(x2, 0.f); x3 = fmaxf(x3, 0.f);
                *(__half2*)(Chx + (size_t)r0 * ldc + c)     = __floats2half2_rn(x0, x1);
                *(__half2*)(Chx + (size_t)(r0+8) * ldc + c) = __floats2half2_rn(x2, x3);
            } else if (MODE == 3) {
                *(__half2*)(Chx + (size_t)r0 * ldc + c)     = __floats2half2_rn(x0, x1);
                *(__half2*)(Chx + (size_t)(r0+8) * ldc + c) = __floats2half2_rn(x2, x3);
            } else {
                float2 rv0 = *(const float2*)(res + (size_t)r0 * ldc + c);
                float2 rv1 = *(const float2*)(res + (size_t)(r0+8) * ldc + c);
                x0 += rv0.x; x1 += rv0.y; x2 += rv1.x; x3 += rv1.y;
                *(float2*)(C0 + (size_t)r0 * ldc + c)     = make_float2(x0, x1);
                *(float2*)(C0 + (size_t)(r0+8) * ldc + c) = make_float2(x2, x3);
            }
        }
    }
}

// ---------------------------------------------------------------------------
// HMMA flash attention (fp16 in, fp32 accum, causal) -> fp16 z
// CTA: 64 q-rows x one (b,h); 4 warps, 16 q-rows/warp.
// KV tiles of 64, cp.async double buffer, smem rows 144B (conflict-free ldmatrix)
// ---------------------------------------------------------------------------
__global__ void __launch_bounds__(128) attn_hmma(
    const __half* __restrict__ Q, const __half* __restrict__ K,
    const __half* __restrict__ V, __half* __restrict__ Z)
{
    __shared__ __align__(16) __half sQ[64*72];
    __shared__ __align__(16) __half sK[2][64*72];
    __shared__ __align__(16) __half sV[2][64*72];
    const int tid = threadIdx.x, lane = tid & 31, wid = tid >> 5;
    const int qblk = (SEQ/64 - 1) - blockIdx.x;     // heavy blocks first
    const int bh = blockIdx.y, b = bh >> 4, h = bh & 15;
    const uint32_t uQ = smem_to_u32(sQ);
    const uint32_t uK = smem_to_u32(sK);
    const uint32_t uV = smem_to_u32(sV);
    const size_t qbase = ((size_t)(b*SEQ + qblk*64)) * D_MODEL + h * D_HEAD;

    for (int f = tid; f < 512; f += 128) {
        int row = f >> 3, c = f & 7;
        cp16(uQ + row*144 + c*16, Q + qbase + (size_t)row * D_MODEL + c*8);
    }
    auto load_kv = [&](int kt, int buf) {
        size_t base = ((size_t)(b*SEQ + kt*64)) * D_MODEL + h * D_HEAD;
        for (int f = tid; f < 512; f += 128) {
            int row = f >> 3, c = f & 7;
            cp16(uK + buf*(64*144) + row*144 + c*16, K + base + (size_t)row * D_MODEL + c*8);
            cp16(uV + buf*(64*144) + row*144 + c*16, V + base + (size_t)row * D_MODEL + c*8);
        }
    };
    load_kv(0, 0);
    asm volatile("cp.async.commit_group;");

    float oacc[8][4];
#pragma unroll
    for (int i = 0; i < 8; i++)
#pragma unroll
        for (int c = 0; c < 4; c++) oacc[i][c] = 0.f;
    float m0 = -INFINITY, m1 = -INFINITY, l0 = 0.f, l1 = 0.f;
    uint32_t a[4][4];

    const int ntiles = qblk + 1;
    for (int kt = 0; kt < ntiles; kt++) {
        if (kt + 1 < ntiles) {
            load_kv(kt + 1, (kt + 1) & 1);
            asm volatile("cp.async.commit_group;");
            asm volatile("cp.async.wait_group 1;");
        } else {
            asm volatile("cp.async.wait_group 0;");
        }
        __syncthreads();

        if (kt == 0) {
#pragma unroll
            for (int kk = 0; kk < 4; kk++)
                ldmx4(a[kk], uQ + (uint32_t)((wid*16 + (lane & 15))*144 + kk*32 + (lane >> 4)*16));
        }

        // S = Q K^T
        const uint32_t kb0 = uK + (uint32_t)((kt & 1) * (64*144));
        float sc[8][4];
#pragma unroll
        for (int i = 0; i < 8; i++)
#pragma unroll
            for (int c = 0; c < 4; c++) sc[i][c] = 0.f;
#pragma unroll
        for (int kk = 0; kk < 4; kk++) {
            uint32_t kb[4][4];
#pragma unroll
            for (int j = 0; j < 4; j++)
                ldmx4(kb[j], kb0 + (uint32_t)((j*16 + (lane & 15))*144 + kk*32 + (lane >> 4)*16));
#pragma unroll
            for (int j = 0; j < 4; j++) {
                mma16816(sc[2*j],   a[kk], kb[j][0], kb[j][2]);
                mma16816(sc[2*j+1], a[kk], kb[j][1], kb[j][3]);
            }
        }

        // softmax (online)
        const float scale = 0.125f;   // 1/sqrt(64)
        const bool diag = (kt == qblk);
        const int q0 = wid*16 + (lane >> 2);
        float mx0 = m0, mx1 = m1;
#pragma unroll
        for (int nb = 0; nb < 8; nb++) {
#pragma unroll
            for (int c = 0; c < 4; c++) {
                float s = sc[nb][c] * scale;
                if (diag) {
                    int jg = nb*8 + (lane & 3)*2 + (c & 1);
                    int qg = q0 + ((c >> 1) << 3);
                    if (jg > qg) s = -INFINITY;
                }
                sc[nb][c] = s;
            }
            mx0 = fmaxf(mx0, fmaxf(sc[nb][0], sc[nb][1]));
            mx1 = fmaxf(mx1, fmaxf(sc[nb][2], sc[nb][3]));
        }
        mx0 = fmaxf(mx0, __shfl_xor_sync(0xFFFFFFFFu, mx0, 1));
        mx0 = fmaxf(mx0, __shfl_xor_sync(0xFFFFFFFFu, mx0, 2));
        mx1 = fmaxf(mx1, __shfl_xor_sync(0xFFFFFFFFu, mx1, 1));
        mx1 = fmaxf(mx1, __shfl_xor_sync(0xFFFFFFFFu, mx1, 2));
        float fac0 = __expf(m0 - mx0), fac1 = __expf(m1 - mx1);
        m0 = mx0; m1 = mx1;
        float ls0 = 0.f, ls1 = 0.f;
#pragma unroll
        for (int nb = 0; nb < 8; nb++) {
            sc[nb][0] = __expf(sc[nb][0] - mx0);
            sc[nb][1] = __expf(sc[nb][1] - mx0);
            sc[nb][2] = __expf(sc[nb][2] - mx1);
            sc[nb][3] = __expf(sc[nb][3] - mx1);
            ls0 += sc[nb][0] + sc[nb][1];
            ls1 += sc[nb][2] + sc[nb][3];
        }
        l0 = l0 * fac0 + ls0;
        l1 = l1 * fac1 + ls1;
#pragma unroll
        for (int nb = 0; nb < 8; nb++) {
            oacc[nb][0] *= fac0; oacc[nb][1] *= fac0;
            oacc[nb][2] *= fac1; oacc[nb][3] *= fac1;
        }

        // O += P V
        const uint32_t vb0 = uV + (uint32_t)((kt & 1) * (64*144));
#pragma unroll
        for (int kk = 0; kk < 4; kk++) {
            uint32_t pa[4];
            pa[0] = packh2(sc[2*kk][0],   sc[2*kk][1]);
            pa[1] = packh2(sc[2*kk][2],   sc[2*kk][3]);
            pa[2] = packh2(sc[2*kk+1][0], sc[2*kk+1][1]);
            pa[3] = packh2(sc[2*kk+1][2], sc[2*kk+1][3]);
#pragma unroll
            for (int j = 0; j < 4; j++) {
                uint32_t vb[4];
                ldmx4t(vb, vb0 + (uint32_t)((kk*16 + (lane & 15))*144 + j*32 + (lane >> 4)*16));
                mma16816(oacc[2*j],   pa, vb[0], vb[1]);
                mma16816(oacc[2*j+1], pa, vb[2], vb[3]);
            }
        }
        __syncthreads();
    }

    // normalize + store
    l0 += __shfl_xor_sync(0xFFFFFFFFu, l0, 1);
    l0 += __shfl_xor_sync(0xFFFFFFFFu, l0, 2);
    l1 += __shfl_xor_sync(0xFFFFFFFFu, l1, 1);
    l1 += __shfl_xor_sync(0xFFFFFFFFu, l1, 2);
    float i0 = 1.f / l0, i1 = 1.f / l1;
    size_t tok0 = (size_t)(b*SEQ + qblk*64 + wid*16 + (lane >> 2));
    size_t zb0 = tok0 * D_MODEL + h * D_HEAD + (lane & 3)*2;
    size_t zb1 = zb0 + (size_t)8 * D_MODEL;
#pragma unroll
    for (int nb = 0; nb < 8; nb++) {
        *(__half2*)(Z + zb0 + nb*8) = __floats2half2_rn(oacc[nb][0]*i0, oacc[nb][1]*i0);
        *(__half2*)(Z + zb1 + nb*8) = __floats2half2_rn(oacc[nb][2]*i1, oacc[nb][3]*i1);
    }
}

// ---------------------------------------------------------------------------
// launch
// ---------------------------------------------------------------------------
extern "C" void kernel_launch(void* const* d_in, const int* in_sizes, int n_in,
                              void* d_out, int out_size) {
    const float* resid_pre = (const float*)d_in[0];
    const float* ln1_w = (const float*)d_in[1];
    const float* ln1_b = (const float*)d_in[2];
    const float* W_Q   = (const float*)d_in[3];
    const float* b_Q   = (const float*)d_in[4];
    const float* W_K   = (const float*)d_in[5];
    const float* b_K   = (const float*)d_in[6];
    const float* W_V   = (const float*)d_in[7];
    const float* b_V   = (const float*)d_in[8];
    const float* W_O   = (const float*)d_in[9];
    const float* b_O   = (const float*)d_in[10];
    const float* ln2_w = (const float*)d_in[11];
    const float* ln2_b = (const float*)d_in[12];
    const float* W_in  = (const float*)d_in[13];
    const float* b_in  = (const float*)d_in[14];
    const float* W_out = (const float*)d_in[15];
    const float* b_out = (const float*)d_in[16];
    float* out = (float*)d_out;

    __half *p_ln1, *p_q, *p_k, *p_v, *p_z, *p_ln2, *p_mlp, *p_wqkv, *p_wo, *p_win, *p_wout;
    float *p_rmid;

    cudaGetSymbolAddress((void**)&p_ln1,  g_ln1);
    cudaGetSymbolAddress((void**)&p_q,    g_q);
    cudaGetSymbolAddress((void**)&p_k,    g_k);
    cudaGetSymbolAddress((void**)&p_v,    g_v);
    cudaGetSymbolAddress((void**)&p_z,    g_z);
    cudaGetSymbolAddress((void**)&p_rmid, g_rmid);
    cudaGetSymbolAddress((void**)&p_ln2,  g_ln2);
    cudaGetSymbolAddress((void**)&p_mlp,  g_mlp);
    cudaGetSymbolAddress((void**)&p_wqkv, g_wqkv);
    cudaGetSymbolAddress((void**)&p_wo,   g_wo);
    cudaGetSymbolAddress((void**)&p_win,  g_win);
    cudaGetSymbolAddress((void**)&p_wout, g_wout);

    cudaFuncSetAttribute(gemm_h<1,false>, cudaFuncAttributeMaxDynamicSharedMemorySize, GEMM_SMEM);
    cudaFuncSetAttribute(gemm_h<2,false>, cudaFuncAttributeMaxDynamicSharedMemorySize, GEMM_SMEM);
    cudaFuncSetAttribute(gemm_h<3,true >, cudaFuncAttributeMaxDynamicSharedMemorySize, GEMM_SMEM);

    // weight prep: transpose to [N,K] fp16; QKV packed into one [3072,1024] buffer
    transpose_h2<<<dim3(1, 16, 16),  256>>>(W_Q,   p_wqkv,                D_MODEL, D_HEAD);
    transpose_h2<<<dim3(1, 16, 16),  256>>>(W_K,   p_wqkv + 1024*D_MODEL, D_MODEL, D_HEAD);
    transpose_h2<<<dim3(1, 16, 16),  256>>>(W_V,   p_wqkv + 2048*D_MODEL, D_MODEL, D_HEAD);
    transpose_h2<<<dim3(16, 16, 1),  256>>>(W_O,   p_wo,   D_MODEL, D_MODEL);
    transpose_h2<<<dim3(64, 16, 1),  256>>>(W_in,  p_win,  D_MODEL, D_MLP);
    transpose_h2<<<dim3(16, 64, 1),  256>>>(W_out, p_wout, D_MLP,   D_MODEL);

    // 1) LN1 -> fp16
    ln_h_kernel<<<NTOK, 256>>>(resid_pre, ln1_w, ln1_b, p_ln1);

    // 2) fused QKV projection -> fp16 q,k,v (segment-select)
    dim3 gQKV(3*D_MODEL/128, NTOK/128);
    gemm_h<3,true><<<gQKV, 256, GEMM_SMEM>>>(p_ln1, p_wqkv, b_Q, b_K, b_V, nullptr,
                                             nullptr, p_q, p_k, p_v, NTOK, 3*D_MODEL, D_MODEL);

    // 3) HMMA flash attention -> fp16 z
    attn_hmma<<<dim3(SEQ/64, BATCH*N_HEADS), 128>>>(p_q, p_k, p_v, p_z);

    // 4) O projection + residual -> rmid (fp32)
    dim3 gProj(D_MODEL/128, NTOK/128);
    gemm_h<1,false><<<gProj, 256, GEMM_SMEM>>>(p_z, p_wo, b_O, nullptr, nullptr, resid_pre,
                                               p_rmid, nullptr, nullptr, nullptr, NTOK, D_MODEL, D_MODEL);

    // 5) LN2 -> fp16
    ln_h_kernel<<<NTOK, 256>>>(p_rmid, ln2_w, ln2_b, p_ln2);

    // 6) MLP in + ReLU -> fp16
    dim3 gMlp1(D_MLP/128, NTOK/128);
    gemm_h<2,false><<<gMlp1, 256, GEMM_SMEM>>>(p_ln2, p_win, b_in, nullptr, nullptr, nullptr,
                                               nullptr, p_mlp, nullptr, nullptr, NTOK, D_MLP, D_MODEL);

    // 7) MLP out + residual -> output (fp32)
    gemm_h<1,false><<<gProj, 256, GEMM_SMEM>>>(p_mlp, p_wout, b_out, nullptr, nullptr, p_rmid,
                                               out, nullptr, nullptr, nullptr, NTOK, D_MODEL, D_MLP);
}